// round 1
// baseline (speedup 1.0000x reference)
#include <cuda_runtime.h>
#include <cuda_bf16.h>
#include <math.h>

// ---------------------------------------------------------------------------
// DecoderBlock: B=2, S=2048, D_MODEL=1024, D_COND=512, H=16, d=64, FF=4096
// Round 1: fp32 SIMT baseline. 10 launches, static __device__ scratch.
// ---------------------------------------------------------------------------

#define BS_TOK   4096      // B*S
#define DM       1024
#define DC       512
#define DFF      4096
#define NH       16
#define DH       64
#define SEQ      2048

// Scratch (static device globals; no allocation at runtime)
__device__ float g_sc  [BS_TOK * DC];        // silu(cond)
__device__ float g_gb  [BS_TOK * 2 * DM];    // gamma/beta (reused)
__device__ float g_h   [BS_TOK * DM];        // adaln output (reused)
__device__ float g_qkv [BS_TOK * 3 * DM];    // qkv
__device__ float g_attn[BS_TOK * DM];        // attention output
__device__ float g_x2  [BS_TOK * DM];        // post-attn residual stream
__device__ float g_ff  [BS_TOK * DFF];       // gelu(ffn1)

// ---------------------------------------------------------------------------
// silu elementwise: out = x * sigmoid(x)
// ---------------------------------------------------------------------------
__global__ void silu_kernel(const float* __restrict__ in, float* __restrict__ out, int n4) {
    int i = blockIdx.x * blockDim.x + threadIdx.x;
    if (i >= n4) return;
    float4 v = ((const float4*)in)[i];
    v.x = v.x / (1.f + expf(-v.x));
    v.y = v.y / (1.f + expf(-v.y));
    v.z = v.z / (1.f + expf(-v.z));
    v.w = v.w / (1.f + expf(-v.w));
    ((float4*)out)[i] = v;
}

// ---------------------------------------------------------------------------
// AdaLN: one block per row (DM=1024). LayerNorm (no affine) then
// (1+gamma)*xn + beta, gamma=gb[row,0:1024], beta=gb[row,1024:2048]
// ---------------------------------------------------------------------------
__global__ __launch_bounds__(256) void adaln_kernel(
    const float* __restrict__ x, const float* __restrict__ gb, float* __restrict__ out)
{
    int row = blockIdx.x;
    const float* xr = x + (size_t)row * DM;
    int i = threadIdx.x * 4;
    float4 v = *(const float4*)(xr + i);
    float s  = v.x + v.y + v.z + v.w;
    float ss = v.x*v.x + v.y*v.y + v.z*v.z + v.w*v.w;
    #pragma unroll
    for (int o = 16; o > 0; o >>= 1) {
        s  += __shfl_xor_sync(0xffffffffu, s,  o);
        ss += __shfl_xor_sync(0xffffffffu, ss, o);
    }
    __shared__ float sh[16];
    int w = threadIdx.x >> 5, ln = threadIdx.x & 31;
    if (ln == 0) { sh[w] = s; sh[w + 8] = ss; }
    __syncthreads();
    float fs = 0.f, fss = 0.f;
    #pragma unroll
    for (int k = 0; k < 8; k++) { fs += sh[k]; fss += sh[k + 8]; }
    float mu   = fs  * (1.f / DM);
    float var  = fss * (1.f / DM) - mu * mu;
    float rstd = rsqrtf(var + 1e-5f);

    const float* g = gb + (size_t)row * (2 * DM);
    float4 ga = *(const float4*)(g + i);
    float4 be = *(const float4*)(g + DM + i);
    float4 o;
    o.x = (v.x - mu) * rstd * (1.f + ga.x) + be.x;
    o.y = (v.y - mu) * rstd * (1.f + ga.y) + be.y;
    o.z = (v.z - mu) * rstd * (1.f + ga.z) + be.z;
    o.w = (v.w - mu) * rstd * (1.f + ga.w) + be.w;
    *(float4*)(out + (size_t)row * DM + i) = o;
}

// ---------------------------------------------------------------------------
// SGEMM: C[M,N] = A[M,K] @ B[K,N] (+bias) (+exact gelu) (+residual)
// 128x128 tile, BK=16, 256 threads, 8x8 per thread.
// All M,N,K here are multiples of the tile dims (no bounds checks).
// ---------------------------------------------------------------------------
template<bool BIAS, bool GELU, bool RES>
__global__ __launch_bounds__(256) void sgemm_kernel(
    const float* __restrict__ A, const float* __restrict__ B,
    const float* __restrict__ bias, const float* __restrict__ res,
    float* __restrict__ C, int M, int N, int K)
{
    const int tid = threadIdx.x;
    const int bx = blockIdx.x;   // N tile
    const int by = blockIdx.y;   // M tile

    __shared__ float As[16][128];
    __shared__ float Bs[16][128];

    float acc[8][8];
    #pragma unroll
    for (int i = 0; i < 8; i++)
        #pragma unroll
        for (int j = 0; j < 8; j++) acc[i][j] = 0.f;

    const float* Ab = A + (size_t)(by * 128) * K;
    const float* Bb = B + bx * 128;

    const int ty = tid >> 4;   // 0..15
    const int tx = tid & 15;   // 0..15

    for (int k0 = 0; k0 < K; k0 += 16) {
        // Load A tile (128 rows x 16 k), store transposed
        #pragma unroll
        for (int t = 0; t < 2; t++) {
            int idx = tid + t * 256;          // 0..511
            int r = idx >> 2;                 // 0..127
            int c = (idx & 3) * 4;            // 0,4,8,12
            float4 v = *(const float4*)(Ab + (size_t)r * K + k0 + c);
            As[c + 0][r] = v.x; As[c + 1][r] = v.y;
            As[c + 2][r] = v.z; As[c + 3][r] = v.w;
        }
        // Load B tile (16 k x 128 cols)
        #pragma unroll
        for (int t = 0; t < 2; t++) {
            int idx = tid + t * 256;
            int r = idx >> 5;                 // 0..15
            int c = (idx & 31) * 4;           // 0..124
            *(float4*)&Bs[r][c] = *(const float4*)(Bb + (size_t)(k0 + r) * N + c);
        }
        __syncthreads();

        #pragma unroll
        for (int kk = 0; kk < 16; kk++) {
            float4 a0 = *(const float4*)&As[kk][ty * 8];
            float4 a1 = *(const float4*)&As[kk][ty * 8 + 4];
            float4 b0 = *(const float4*)&Bs[kk][tx * 8];
            float4 b1 = *(const float4*)&Bs[kk][tx * 8 + 4];
            float ar[8] = {a0.x,a0.y,a0.z,a0.w,a1.x,a1.y,a1.z,a1.w};
            float br[8] = {b0.x,b0.y,b0.z,b0.w,b1.x,b1.y,b1.z,b1.w};
            #pragma unroll
            for (int i = 0; i < 8; i++)
                #pragma unroll
                for (int j = 0; j < 8; j++)
                    acc[i][j] += ar[i] * br[j];
        }
        __syncthreads();
    }

    // Epilogue
    #pragma unroll
    for (int i = 0; i < 8; i++) {
        int row = by * 128 + ty * 8 + i;
        #pragma unroll
        for (int j = 0; j < 8; j++) {
            int col = bx * 128 + tx * 8 + j;
            float v = acc[i][j];
            if (BIAS) v += bias[col];
            if (GELU) v = 0.5f * v * (1.f + erff(v * 0.70710678118654752f));
            if (RES)  v += res[(size_t)row * N + col];
            C[(size_t)row * N + col] = v;
        }
    }
}

// ---------------------------------------------------------------------------
// Attention: one thread per query, block = 128 queries for one (b,h).
// Online softmax over K tiles of 32 staged in SMEM (broadcast reads).
// qkv layout: [tok, 3*DM]: q at [0,DM), k at [DM,2DM), v at [2DM,3DM);
// head h occupies cols h*64..h*64+63 of each segment.
// ---------------------------------------------------------------------------
__global__ __launch_bounds__(128) void attn_kernel(
    const float* __restrict__ qkv, float* __restrict__ out)
{
    const int b = blockIdx.z;
    const int h = blockIdx.y;
    const int q = blockIdx.x * 128 + threadIdx.x;
    const int tok = b * SEQ + q;

    const float* qp = qkv + (size_t)tok * (3 * DM) + h * DH;
    float qr[DH];
    #pragma unroll
    for (int i = 0; i < DH; i += 4) {
        float4 v = *(const float4*)(qp + i);
        qr[i] = v.x; qr[i+1] = v.y; qr[i+2] = v.z; qr[i+3] = v.w;
    }

    __shared__ float Ks[32][DH];
    __shared__ float Vs[32][DH];

    float acc[DH];
    #pragma unroll
    for (int i = 0; i < DH; i++) acc[i] = 0.f;
    float m = -1e30f, l = 0.f;

    for (int kb = 0; kb < SEQ; kb += 32) {
        // cooperative load of K,V tile: 32x64 floats each = 512 float4 each
        #pragma unroll
        for (int t = 0; t < 4; t++) {
            int idx = threadIdx.x + t * 128;   // 0..511
            int j = idx >> 4;                  // 0..31
            int c = (idx & 15) * 4;            // 0..60
            const float* base = qkv + (size_t)(b * SEQ + kb + j) * (3 * DM) + h * DH + c;
            *(float4*)&Ks[j][c] = *(const float4*)(base + DM);
            *(float4*)&Vs[j][c] = *(const float4*)(base + 2 * DM);
        }
        __syncthreads();

        float s[32];
        #pragma unroll
        for (int j = 0; j < 32; j++) {
            float d0 = 0.f;
            #pragma unroll
            for (int t = 0; t < DH; t += 4) {
                float4 kv = *(const float4*)&Ks[j][t];
                d0 += qr[t] * kv.x + qr[t+1] * kv.y + qr[t+2] * kv.z + qr[t+3] * kv.w;
            }
            s[j] = d0 * 0.125f;   // 1/sqrt(64)
        }
        float mt = m;
        #pragma unroll
        for (int j = 0; j < 32; j++) mt = fmaxf(mt, s[j]);
        float corr = __expf(m - mt);
        m = mt;
        l *= corr;
        #pragma unroll
        for (int i = 0; i < DH; i++) acc[i] *= corr;

        #pragma unroll
        for (int j = 0; j < 32; j++) {
            float p = __expf(s[j] - m);
            l += p;
            #pragma unroll
            for (int i = 0; i < DH; i += 4) {
                float4 vv = *(const float4*)&Vs[j][i];
                acc[i]   += p * vv.x;
                acc[i+1] += p * vv.y;
                acc[i+2] += p * vv.z;
                acc[i+3] += p * vv.w;
            }
        }
        __syncthreads();
    }

    float inv = 1.f / l;
    float* op = out + (size_t)tok * DM + h * DH;
    #pragma unroll
    for (int i = 0; i < DH; i += 4) {
        float4 v;
        v.x = acc[i] * inv; v.y = acc[i+1] * inv;
        v.z = acc[i+2] * inv; v.w = acc[i+3] * inv;
        *(float4*)(op + i) = v;
    }
}

// ---------------------------------------------------------------------------
// Launch
// ---------------------------------------------------------------------------
extern "C" void kernel_launch(void* const* d_in, const int* in_sizes, int n_in,
                              void* d_out, int out_size)
{
    const float* x          = (const float*)d_in[0];
    const float* cond       = (const float*)d_in[1];
    const float* p1_w       = (const float*)d_in[2];
    const float* p1_b       = (const float*)d_in[3];
    const float* qkv_w      = (const float*)d_in[4];
    const float* attn_out_w = (const float*)d_in[5];
    const float* p2_w       = (const float*)d_in[6];
    const float* p2_b       = (const float*)d_in[7];
    const float* ffn_w1     = (const float*)d_in[8];
    const float* ffn_b1     = (const float*)d_in[9];
    const float* ffn_w2     = (const float*)d_in[10];
    const float* ffn_b2     = (const float*)d_in[11];
    float* out = (float*)d_out;

    float *sc, *gb, *h, *qkv, *attn, *x2, *ff;
    cudaGetSymbolAddress((void**)&sc,   g_sc);
    cudaGetSymbolAddress((void**)&gb,   g_gb);
    cudaGetSymbolAddress((void**)&h,    g_h);
    cudaGetSymbolAddress((void**)&qkv,  g_qkv);
    cudaGetSymbolAddress((void**)&attn, g_attn);
    cudaGetSymbolAddress((void**)&x2,   g_x2);
    cudaGetSymbolAddress((void**)&ff,   g_ff);

    // 1. sc = silu(cond)
    silu_kernel<<<(BS_TOK * DC / 4 + 255) / 256, 256>>>(cond, sc, BS_TOK * DC / 4);
    // 2. gb = sc @ p1_w + p1_b              (4096 x 2048 x 512)
    sgemm_kernel<true, false, false><<<dim3(2048 / 128, BS_TOK / 128), 256>>>(
        sc, p1_w, p1_b, nullptr, gb, BS_TOK, 2048, DC);
    // 3. h = adaln(x, gb)
    adaln_kernel<<<BS_TOK, 256>>>(x, gb, h);
    // 4. qkv = h @ qkv_w                    (4096 x 3072 x 1024)
    sgemm_kernel<false, false, false><<<dim3(3072 / 128, BS_TOK / 128), 256>>>(
        h, qkv_w, nullptr, nullptr, qkv, BS_TOK, 3072, DM);
    // 5. attention
    attn_kernel<<<dim3(SEQ / 128, NH, 2), 128>>>(qkv, attn);
    // 6. x2 = x + attn @ attn_out_w         (4096 x 1024 x 1024)
    sgemm_kernel<false, false, true><<<dim3(1024 / 128, BS_TOK / 128), 256>>>(
        attn, attn_out_w, nullptr, x, x2, BS_TOK, 1024, DM);
    // 7. gb = sc @ p2_w + p2_b              (4096 x 2048 x 512)
    sgemm_kernel<true, false, false><<<dim3(2048 / 128, BS_TOK / 128), 256>>>(
        sc, p2_w, p2_b, nullptr, gb, BS_TOK, 2048, DC);
    // 8. h = adaln(x2, gb)
    adaln_kernel<<<BS_TOK, 256>>>(x2, gb, h);
    // 9. ff = gelu(h @ ffn_w1 + ffn_b1)     (4096 x 4096 x 1024)
    sgemm_kernel<true, true, false><<<dim3(DFF / 128, BS_TOK / 128), 256>>>(
        h, ffn_w1, ffn_b1, nullptr, ff, BS_TOK, DFF, DM);
    // 10. out = x2 + ff @ ffn_w2 + ffn_b2   (4096 x 1024 x 4096)
    sgemm_kernel<true, false, true><<<dim3(1024 / 128, BS_TOK / 128), 256>>>(
        ff, ffn_w2, ffn_b2, x2, out, BS_TOK, 1024, DFF);
}

// round 3
// speedup vs baseline: 2.0104x; 2.0104x over previous
#include <cuda_runtime.h>
#include <cuda_bf16.h>
#include <math.h>
#include <stdint.h>

// ---------------------------------------------------------------------------
// DecoderBlock: B=2, S=2048, D_MODEL=1024, D_COND=512, H=16, d=64, FF=4096
// Round 3: mma.sync tf32 GEMMs (legacy HMMA path — tcgen05 PTX unavailable
// under compute_103 virtual arch), cp.async 3-stage pipeline, SW128 swizzle.
// ---------------------------------------------------------------------------

#define BS_TOK   4096
#define DM       1024
#define DC       512
#define DFF      4096
#define NH       16
#define DH       64
#define SEQ      2048

// ---------------- scratch ---------------------------------------------------
__device__ float g_sc  [BS_TOK * DC];
__device__ float g_gb  [BS_TOK * 2 * DM];
__device__ float g_h   [BS_TOK * DM];
__device__ float g_qkv [BS_TOK * 3 * DM];
__device__ float g_attn[BS_TOK * DM];
__device__ float g_x2  [BS_TOK * DM];
__device__ float g_ff  [BS_TOK * DFF];
__device__ float g_wt_p1 [2 * DM * DC];
__device__ float g_wt_qkv[3 * DM * DM];
__device__ float g_wt_ao [DM * DM];
__device__ float g_wt_p2 [2 * DM * DC];
__device__ float g_wt_f1 [DFF * DM];
__device__ float g_wt_f2 [DM * DFF];

// ---------------- helpers ---------------------------------------------------
__device__ __forceinline__ uint32_t smem_u32(const void* p) {
    uint32_t a;
    asm("{ .reg .u64 t; cvta.to.shared.u64 t, %1; cvt.u32.u64 %0, t; }"
        : "=r"(a) : "l"(p));
    return a;
}
__device__ __forceinline__ float f2tf32f(float f) {
    uint32_t r;
    asm("cvt.rna.tf32.f32 %0, %1;" : "=r"(r) : "f"(f));
    return __uint_as_float(r);
}
__device__ __forceinline__ void cp_async16(uint32_t dst, const void* src) {
    asm volatile("cp.async.cg.shared.global [%0], [%1], 16;"
                 :: "r"(dst), "l"(src) : "memory");
}
#define CP_COMMIT() asm volatile("cp.async.commit_group;" ::: "memory")
#define CP_WAIT(n)  asm volatile("cp.async.wait_group %0;" :: "n"(n) : "memory")

__device__ __forceinline__ void mma_tf32(float* c, const uint32_t* a, const uint32_t* b) {
    asm volatile("mma.sync.aligned.m16n8k8.row.col.f32.tf32.tf32.f32 "
        "{%0,%1,%2,%3}, {%4,%5,%6,%7}, {%8,%9}, {%0,%1,%2,%3};"
        : "+f"(c[0]), "+f"(c[1]), "+f"(c[2]), "+f"(c[3])
        : "r"(a[0]), "r"(a[1]), "r"(a[2]), "r"(a[3]), "r"(b[0]), "r"(b[1]));
}

#define SWZ(off) ((off) ^ (((off) >> 3) & 0x70))

// ---------------------------------------------------------------------------
// tf32 mma GEMM: C[M,N] = A[M,K] @ Bt[N,K]^T (+bias)(+gelu)(+res)
// BM=BN=128, BK=32, 256 threads, 8 warps of 64x32, 3-stage cp.async.
// A must be tf32-rounded fp32 (producers round), Bt pre-rounded.
// ---------------------------------------------------------------------------
#define TG_SMEM (3 * 16384 * 2)

template<int BIAS, int GELU, int RES>
__global__ __launch_bounds__(256) void tgemm(
    const float* __restrict__ A, const float* __restrict__ Bt,
    const float* __restrict__ bias, const float* __restrict__ res,
    float* __restrict__ C, int M, int N, int K)
{
    extern __shared__ __align__(1024) char smem_raw[];
    const uint32_t sA = smem_u32(smem_raw);          // 3 x 16KB A buffers
    const uint32_t sB = sA + 3 * 16384;              // 3 x 16KB B buffers

    const int tid  = threadIdx.x;
    const int wid  = tid >> 5;
    const int lane = tid & 31;
    const int bx = blockIdx.x, by = blockIdx.y;

    const float* Ab = A  + (size_t)(by * 128) * K;
    const float* Bb = Bt + (size_t)(bx * 128) * K;
    const int S = K >> 5;

    const int lr = tid >> 3;          // loader row 0..31 (per t-step base)
    const int lc = tid & 7;           // loader 16B chunk 0..7

    auto issue = [&](int s, int st) {
        const int k0 = s * 32;
        const uint32_t ao = sA + st * 16384;
        const uint32_t bo = sB + st * 16384;
        #pragma unroll
        for (int t = 0; t < 4; t++) {
            int r = lr + t * 32;
            uint32_t off = SWZ((uint32_t)(r * 128 + lc * 16));
            cp_async16(ao + off, Ab + (size_t)r * K + k0 + lc * 4);
            cp_async16(bo + off, Bb + (size_t)r * K + k0 + lc * 4);
        }
        CP_COMMIT();
    };

    float acc[4][4][4];
    #pragma unroll
    for (int i = 0; i < 4; i++)
        #pragma unroll
        for (int j = 0; j < 4; j++)
            #pragma unroll
            for (int k = 0; k < 4; k++) acc[i][j][k] = 0.f;

    const int wm = (wid >> 2) * 64;   // 0 / 64
    const int wn = (wid & 3) * 32;    // 0 / 32 / 64 / 96
    const int g  = lane >> 2;         // 0..7
    const int tg = lane & 3;          // 0..3

    issue(0, 0);
    issue(1, 1);

    for (int s = 0; s < S; s++) {
        if (s + 1 < S) { CP_WAIT(1); } else { CP_WAIT(0); }
        __syncthreads();
        if (s + 2 < S) issue(s + 2, (s + 2) % 3);

        const uint32_t aBase = sA + (s % 3) * 16384;
        const uint32_t bBase = sB + (s % 3) * 16384;
        #pragma unroll
        for (int kk = 0; kk < 4; kk++) {
            const uint32_t c0 = (uint32_t)(((2 * kk) ^ g) * 16 + tg * 4);
            const uint32_t c1 = (uint32_t)(((2 * kk + 1) ^ g) * 16 + tg * 4);
            uint32_t a[4][4], b[4][2];
            #pragma unroll
            for (int mt = 0; mt < 4; mt++) {
                const uint32_t r0 = aBase + (uint32_t)((wm + mt * 16 + g) * 128);
                asm volatile("ld.shared.b32 %0,[%1];" : "=r"(a[mt][0]) : "r"(r0 + c0));
                asm volatile("ld.shared.b32 %0,[%1];" : "=r"(a[mt][1]) : "r"(r0 + 1024 + c0));
                asm volatile("ld.shared.b32 %0,[%1];" : "=r"(a[mt][2]) : "r"(r0 + c1));
                asm volatile("ld.shared.b32 %0,[%1];" : "=r"(a[mt][3]) : "r"(r0 + 1024 + c1));
            }
            #pragma unroll
            for (int nt = 0; nt < 4; nt++) {
                const uint32_t rb = bBase + (uint32_t)((wn + nt * 8 + g) * 128);
                asm volatile("ld.shared.b32 %0,[%1];" : "=r"(b[nt][0]) : "r"(rb + c0));
                asm volatile("ld.shared.b32 %0,[%1];" : "=r"(b[nt][1]) : "r"(rb + c1));
            }
            #pragma unroll
            for (int mt = 0; mt < 4; mt++)
                #pragma unroll
                for (int nt = 0; nt < 4; nt++)
                    mma_tf32(acc[mt][nt], a[mt], b[nt]);
        }
        __syncthreads();
    }

    // ---- epilogue ----
    #pragma unroll
    for (int mt = 0; mt < 4; mt++) {
        const int row0 = by * 128 + wm + mt * 16 + g;
        #pragma unroll
        for (int half = 0; half < 2; half++) {
            const int row = row0 + half * 8;
            float* Cr = C + (size_t)row * N;
            const float* Rr = RES ? (res + (size_t)row * N) : (const float*)0;
            #pragma unroll
            for (int nt = 0; nt < 4; nt++) {
                const int col = bx * 128 + wn + nt * 8 + tg * 2;
                float v0 = acc[mt][nt][half * 2 + 0];
                float v1 = acc[mt][nt][half * 2 + 1];
                if (BIAS) { v0 += bias[col]; v1 += bias[col + 1]; }
                if (GELU) {
                    v0 = 0.5f * v0 * (1.f + erff(v0 * 0.70710678118654752f));
                    v1 = 0.5f * v1 * (1.f + erff(v1 * 0.70710678118654752f));
                    v0 = f2tf32f(v0);   // feeds next GEMM's A side
                    v1 = f2tf32f(v1);
                }
                if (RES) { v0 += Rr[col]; v1 += Rr[col + 1]; }
                float2 o; o.x = v0; o.y = v1;
                *(float2*)(Cr + col) = o;
            }
        }
    }
}

// ---------------------------------------------------------------------------
// Weight transpose + tf32 rounding: Wt[n,k] = tf32(W[k,n])
// ---------------------------------------------------------------------------
__global__ __launch_bounds__(256) void transpose_tf32(
    const float* __restrict__ W, float* __restrict__ Wt, int K, int N)
{
    __shared__ float t[32][33];
    int n0 = blockIdx.x * 32, k0 = blockIdx.y * 32;
    int tx = threadIdx.x & 31, ty = threadIdx.x >> 5;
    #pragma unroll
    for (int i = 0; i < 32; i += 8)
        t[ty + i][tx] = W[(size_t)(k0 + ty + i) * N + n0 + tx];
    __syncthreads();
    #pragma unroll
    for (int i = 0; i < 32; i += 8)
        Wt[(size_t)(n0 + ty + i) * K + k0 + tx] = f2tf32f(t[tx][ty + i]);
}

// ---------------------------------------------------------------------------
// silu (tf32-rounded output — feeds GEMMs as A operand)
// ---------------------------------------------------------------------------
__global__ void silu_kernel(const float* __restrict__ in, float* __restrict__ out, int n4) {
    int i = blockIdx.x * blockDim.x + threadIdx.x;
    if (i >= n4) return;
    float4 v = ((const float4*)in)[i];
    v.x = f2tf32f(v.x / (1.f + expf(-v.x)));
    v.y = f2tf32f(v.y / (1.f + expf(-v.y)));
    v.z = f2tf32f(v.z / (1.f + expf(-v.z)));
    v.w = f2tf32f(v.w / (1.f + expf(-v.w)));
    ((float4*)out)[i] = v;
}

// ---------------------------------------------------------------------------
// AdaLN (tf32-rounded output — feeds qkv / ffn1 GEMMs)
// ---------------------------------------------------------------------------
__global__ __launch_bounds__(256) void adaln_kernel(
    const float* __restrict__ x, const float* __restrict__ gb, float* __restrict__ out)
{
    int row = blockIdx.x;
    const float* xr = x + (size_t)row * DM;
    int i = threadIdx.x * 4;
    float4 v = *(const float4*)(xr + i);
    float s  = v.x + v.y + v.z + v.w;
    float ss = v.x*v.x + v.y*v.y + v.z*v.z + v.w*v.w;
    #pragma unroll
    for (int o = 16; o > 0; o >>= 1) {
        s  += __shfl_xor_sync(0xffffffffu, s,  o);
        ss += __shfl_xor_sync(0xffffffffu, ss, o);
    }
    __shared__ float sh[16];
    int w = threadIdx.x >> 5, ln = threadIdx.x & 31;
    if (ln == 0) { sh[w] = s; sh[w + 8] = ss; }
    __syncthreads();
    float fs = 0.f, fss = 0.f;
    #pragma unroll
    for (int k = 0; k < 8; k++) { fs += sh[k]; fss += sh[k + 8]; }
    float mu   = fs  * (1.f / DM);
    float var  = fss * (1.f / DM) - mu * mu;
    float rstd = rsqrtf(var + 1e-5f);

    const float* gp = gb + (size_t)row * (2 * DM);
    float4 ga = *(const float4*)(gp + i);
    float4 be = *(const float4*)(gp + DM + i);
    float4 o;
    o.x = f2tf32f((v.x - mu) * rstd * (1.f + ga.x) + be.x);
    o.y = f2tf32f((v.y - mu) * rstd * (1.f + ga.y) + be.y);
    o.z = f2tf32f((v.z - mu) * rstd * (1.f + ga.z) + be.z);
    o.w = f2tf32f((v.w - mu) * rstd * (1.f + ga.w) + be.w);
    *(float4*)(out + (size_t)row * DM + i) = o;
}

// ---------------------------------------------------------------------------
// Attention (fp32 SIMT; tf32-rounded output — feeds attn_out GEMM)
// ---------------------------------------------------------------------------
__global__ __launch_bounds__(128) void attn_kernel(
    const float* __restrict__ qkv, float* __restrict__ out)
{
    const int b = blockIdx.z;
    const int h = blockIdx.y;
    const int q = blockIdx.x * 128 + threadIdx.x;
    const int tok = b * SEQ + q;

    const float* qp = qkv + (size_t)tok * (3 * DM) + h * DH;
    float qr[DH];
    #pragma unroll
    for (int i = 0; i < DH; i += 4) {
        float4 v = *(const float4*)(qp + i);
        qr[i] = v.x; qr[i+1] = v.y; qr[i+2] = v.z; qr[i+3] = v.w;
    }

    __shared__ float Ks[32][DH];
    __shared__ float Vs[32][DH];

    float acc[DH];
    #pragma unroll
    for (int i = 0; i < DH; i++) acc[i] = 0.f;
    float m = -1e30f, l = 0.f;

    for (int kb = 0; kb < SEQ; kb += 32) {
        #pragma unroll
        for (int t = 0; t < 4; t++) {
            int idx = threadIdx.x + t * 128;
            int j = idx >> 4;
            int c = (idx & 15) * 4;
            const float* base = qkv + (size_t)(b * SEQ + kb + j) * (3 * DM) + h * DH + c;
            *(float4*)&Ks[j][c] = *(const float4*)(base + DM);
            *(float4*)&Vs[j][c] = *(const float4*)(base + 2 * DM);
        }
        __syncthreads();

        float s[32];
        #pragma unroll
        for (int j = 0; j < 32; j++) {
            float d0 = 0.f;
            #pragma unroll
            for (int t = 0; t < DH; t += 4) {
                float4 kv = *(const float4*)&Ks[j][t];
                d0 += qr[t] * kv.x + qr[t+1] * kv.y + qr[t+2] * kv.z + qr[t+3] * kv.w;
            }
            s[j] = d0 * 0.125f;
        }
        float mt = m;
        #pragma unroll
        for (int j = 0; j < 32; j++) mt = fmaxf(mt, s[j]);
        float corr = __expf(m - mt);
        m = mt;
        l *= corr;
        #pragma unroll
        for (int i = 0; i < DH; i++) acc[i] *= corr;

        #pragma unroll
        for (int j = 0; j < 32; j++) {
            float p = __expf(s[j] - m);
            l += p;
            #pragma unroll
            for (int i = 0; i < DH; i += 4) {
                float4 vv = *(const float4*)&Vs[j][i];
                acc[i]   += p * vv.x;
                acc[i+1] += p * vv.y;
                acc[i+2] += p * vv.z;
                acc[i+3] += p * vv.w;
            }
        }
        __syncthreads();
    }

    float inv = 1.f / l;
    float* op = out + (size_t)tok * DM + h * DH;
    #pragma unroll
    for (int i = 0; i < DH; i += 4) {
        float4 v;
        v.x = f2tf32f(acc[i]   * inv);
        v.y = f2tf32f(acc[i+1] * inv);
        v.z = f2tf32f(acc[i+2] * inv);
        v.w = f2tf32f(acc[i+3] * inv);
        *(float4*)(op + i) = v;
    }
}

// ---------------------------------------------------------------------------
// Launch
// ---------------------------------------------------------------------------
extern "C" void kernel_launch(void* const* d_in, const int* in_sizes, int n_in,
                              void* d_out, int out_size)
{
    const float* x          = (const float*)d_in[0];
    const float* cond       = (const float*)d_in[1];
    const float* p1_w       = (const float*)d_in[2];
    const float* p1_b       = (const float*)d_in[3];
    const float* qkv_w      = (const float*)d_in[4];
    const float* attn_out_w = (const float*)d_in[5];
    const float* p2_w       = (const float*)d_in[6];
    const float* p2_b       = (const float*)d_in[7];
    const float* ffn_w1     = (const float*)d_in[8];
    const float* ffn_b1     = (const float*)d_in[9];
    const float* ffn_w2     = (const float*)d_in[10];
    const float* ffn_b2     = (const float*)d_in[11];
    float* out = (float*)d_out;

    float *sc, *gb, *h, *qkv, *attn, *x2, *ff;
    float *wt_p1, *wt_qkv, *wt_ao, *wt_p2, *wt_f1, *wt_f2;
    cudaGetSymbolAddress((void**)&sc,    g_sc);
    cudaGetSymbolAddress((void**)&gb,    g_gb);
    cudaGetSymbolAddress((void**)&h,     g_h);
    cudaGetSymbolAddress((void**)&qkv,   g_qkv);
    cudaGetSymbolAddress((void**)&attn,  g_attn);
    cudaGetSymbolAddress((void**)&x2,    g_x2);
    cudaGetSymbolAddress((void**)&ff,    g_ff);
    cudaGetSymbolAddress((void**)&wt_p1,  g_wt_p1);
    cudaGetSymbolAddress((void**)&wt_qkv, g_wt_qkv);
    cudaGetSymbolAddress((void**)&wt_ao,  g_wt_ao);
    cudaGetSymbolAddress((void**)&wt_p2,  g_wt_p2);
    cudaGetSymbolAddress((void**)&wt_f1,  g_wt_f1);
    cudaGetSymbolAddress((void**)&wt_f2,  g_wt_f2);

    cudaFuncSetAttribute(tgemm<1,0,0>, cudaFuncAttributeMaxDynamicSharedMemorySize, TG_SMEM);
    cudaFuncSetAttribute(tgemm<0,0,0>, cudaFuncAttributeMaxDynamicSharedMemorySize, TG_SMEM);
    cudaFuncSetAttribute(tgemm<0,0,1>, cudaFuncAttributeMaxDynamicSharedMemorySize, TG_SMEM);
    cudaFuncSetAttribute(tgemm<1,1,0>, cudaFuncAttributeMaxDynamicSharedMemorySize, TG_SMEM);
    cudaFuncSetAttribute(tgemm<1,0,1>, cudaFuncAttributeMaxDynamicSharedMemorySize, TG_SMEM);

    // Weight transposes ([K,N] -> [N,K], tf32-rounded)
    transpose_tf32<<<dim3(2048/32,  512/32), 256>>>(p1_w,       wt_p1,  512,  2048);
    transpose_tf32<<<dim3(3072/32, 1024/32), 256>>>(qkv_w,      wt_qkv, 1024, 3072);
    transpose_tf32<<<dim3(1024/32, 1024/32), 256>>>(attn_out_w, wt_ao,  1024, 1024);
    transpose_tf32<<<dim3(2048/32,  512/32), 256>>>(p2_w,       wt_p2,  512,  2048);
    transpose_tf32<<<dim3(4096/32, 1024/32), 256>>>(ffn_w1,     wt_f1,  1024, 4096);
    transpose_tf32<<<dim3(1024/32, 4096/32), 256>>>(ffn_w2,     wt_f2,  4096, 1024);

    // 1. sc = silu(cond)  [tf32-rounded]
    silu_kernel<<<(BS_TOK * DC / 4 + 255) / 256, 256>>>(cond, sc, BS_TOK * DC / 4);
    // 2. gb = sc @ p1_w + p1_b
    tgemm<1,0,0><<<dim3(2048/128, BS_TOK/128), 256, TG_SMEM>>>(
        sc, wt_p1, p1_b, nullptr, gb, BS_TOK, 2048, DC);
    // 3. h = adaln(x, gb)  [tf32-rounded]
    adaln_kernel<<<BS_TOK, 256>>>(x, gb, h);
    // 4. qkv = h @ qkv_w
    tgemm<0,0,0><<<dim3(3072/128, BS_TOK/128), 256, TG_SMEM>>>(
        h, wt_qkv, nullptr, nullptr, qkv, BS_TOK, 3072, DM);
    // 5. attention  [tf32-rounded output]
    attn_kernel<<<dim3(SEQ/128, NH, 2), 128>>>(qkv, attn);
    // 6. x2 = x + attn @ attn_out_w
    tgemm<0,0,1><<<dim3(1024/128, BS_TOK/128), 256, TG_SMEM>>>(
        attn, wt_ao, nullptr, x, x2, BS_TOK, 1024, DM);
    // 7. gb = sc @ p2_w + p2_b
    tgemm<1,0,0><<<dim3(2048/128, BS_TOK/128), 256, TG_SMEM>>>(
        sc, wt_p2, p2_b, nullptr, gb, BS_TOK, 2048, DC);
    // 8. h = adaln(x2, gb)  [tf32-rounded]
    adaln_kernel<<<BS_TOK, 256>>>(x2, gb, h);
    // 9. ff = gelu(h @ ffn_w1 + ffn_b1)  [tf32-rounded in epilogue]
    tgemm<1,1,0><<<dim3(DFF/128, BS_TOK/128), 256, TG_SMEM>>>(
        h, wt_f1, ffn_b1, nullptr, ff, BS_TOK, DFF, DM);
    // 10. out = x2 + ff @ ffn_w2 + ffn_b2
    tgemm<1,0,1><<<dim3(1024/128, BS_TOK/128), 256, TG_SMEM>>>(
        ff, wt_f2, ffn_b2, x2, out, BS_TOK, 1024, DFF);
}

// round 5
// speedup vs baseline: 3.5857x; 1.7836x over previous
#include <cuda_runtime.h>
#include <cuda_bf16.h>
#include <math.h>
#include <stdint.h>

// ---------------------------------------------------------------------------
// DecoderBlock: B=2, S=2048, D_MODEL=1024, D_COND=512, H=16, d=64, FF=4096
// Round 5: fix flash-attn loader strides (R4 loaded only 16/64 feature cols).
// ---------------------------------------------------------------------------

#define BS_TOK   4096
#define DM       1024
#define DC       512
#define DFF      4096
#define NH       16
#define DH       64
#define SEQ      2048

// ---------------- scratch ---------------------------------------------------
__device__ float g_sc  [BS_TOK * DC];
__device__ float g_gb  [BS_TOK * 2 * DM];
__device__ float g_h   [BS_TOK * DM];
__device__ float g_qkv [BS_TOK * 3 * DM];
__device__ float g_attn[BS_TOK * DM];
__device__ float g_x2  [BS_TOK * DM];
__device__ float g_ff  [BS_TOK * DFF];
__device__ float g_wt_p1 [2 * DM * DC];
__device__ float g_wt_qkv[3 * DM * DM];
__device__ float g_wt_ao [DM * DM];
__device__ float g_wt_p2 [2 * DM * DC];
__device__ float g_wt_f1 [DFF * DM];
__device__ float g_wt_f2 [DM * DFF];

// ---------------- helpers ---------------------------------------------------
__device__ __forceinline__ uint32_t smem_u32(const void* p) {
    uint32_t a;
    asm("{ .reg .u64 t; cvta.to.shared.u64 t, %1; cvt.u32.u64 %0, t; }"
        : "=r"(a) : "l"(p));
    return a;
}
__device__ __forceinline__ float f2tf32f(float f) {
    uint32_t r;
    asm("cvt.rna.tf32.f32 %0, %1;" : "=r"(r) : "f"(f));
    return __uint_as_float(r);
}
__device__ __forceinline__ void cp_async16(uint32_t dst, const void* src) {
    asm volatile("cp.async.cg.shared.global [%0], [%1], 16;"
                 :: "r"(dst), "l"(src) : "memory");
}
#define CP_COMMIT() asm volatile("cp.async.commit_group;" ::: "memory")
#define CP_WAIT(n)  asm volatile("cp.async.wait_group %0;" :: "n"(n) : "memory")

__device__ __forceinline__ void mma_tf32(float* c, const uint32_t* a, const uint32_t* b) {
    asm volatile("mma.sync.aligned.m16n8k8.row.col.f32.tf32.tf32.f32 "
        "{%0,%1,%2,%3}, {%4,%5,%6,%7}, {%8,%9}, {%0,%1,%2,%3};"
        : "+f"(c[0]), "+f"(c[1]), "+f"(c[2]), "+f"(c[3])
        : "r"(a[0]), "r"(a[1]), "r"(a[2]), "r"(a[3]), "r"(b[0]), "r"(b[1]));
}

#define SWZ(off) ((off) ^ (((off) >> 3) & 0x70))
// 256B-row swizzle (64 floats/row)
#define AXS(r, c) ((uint32_t)((r) * 256 + ((((c) ^ ((((r) & 7)) << 2))) << 2)))
// 128B-row swizzle (32 floats/row)
#define PXS(r, c) ((uint32_t)((r) * 128 + ((((c) ^ ((((r) & 7)) << 2))) << 2)))

// ---------------------------------------------------------------------------
// tf32 mma GEMM: C[M,N] = A[M,K] @ Bt[N,K]^T (+bias)(+gelu)(+res)
// ---------------------------------------------------------------------------
#define TG_SMEM (3 * 16384 * 2)

template<int BIAS, int GELU, int RES>
__global__ __launch_bounds__(256) void tgemm(
    const float* __restrict__ A, const float* __restrict__ Bt,
    const float* __restrict__ bias, const float* __restrict__ res,
    float* __restrict__ C, int M, int N, int K)
{
    extern __shared__ __align__(1024) char smem_raw[];
    const uint32_t sA = smem_u32(smem_raw);
    const uint32_t sB = sA + 3 * 16384;

    const int tid  = threadIdx.x;
    const int wid  = tid >> 5;
    const int lane = tid & 31;
    const int bx = blockIdx.x, by = blockIdx.y;

    const float* Ab = A  + (size_t)(by * 128) * K;
    const float* Bb = Bt + (size_t)(bx * 128) * K;
    const int S = K >> 5;

    const int lr = tid >> 3;
    const int lc = tid & 7;

    auto issue = [&](int s, int st) {
        const int k0 = s * 32;
        const uint32_t ao = sA + st * 16384;
        const uint32_t bo = sB + st * 16384;
        #pragma unroll
        for (int t = 0; t < 4; t++) {
            int r = lr + t * 32;
            uint32_t off = SWZ((uint32_t)(r * 128 + lc * 16));
            cp_async16(ao + off, Ab + (size_t)r * K + k0 + lc * 4);
            cp_async16(bo + off, Bb + (size_t)r * K + k0 + lc * 4);
        }
        CP_COMMIT();
    };

    float acc[4][4][4];
    #pragma unroll
    for (int i = 0; i < 4; i++)
        #pragma unroll
        for (int j = 0; j < 4; j++)
            #pragma unroll
            for (int k = 0; k < 4; k++) acc[i][j][k] = 0.f;

    const int wm = (wid >> 2) * 64;
    const int wn = (wid & 3) * 32;
    const int g  = lane >> 2;
    const int tg = lane & 3;

    issue(0, 0);
    issue(1, 1);

    for (int s = 0; s < S; s++) {
        if (s + 1 < S) { CP_WAIT(1); } else { CP_WAIT(0); }
        __syncthreads();
        if (s + 2 < S) issue(s + 2, (s + 2) % 3);

        const uint32_t aBase = sA + (s % 3) * 16384;
        const uint32_t bBase = sB + (s % 3) * 16384;
        #pragma unroll
        for (int kk = 0; kk < 4; kk++) {
            const uint32_t c0 = (uint32_t)(((2 * kk) ^ g) * 16 + tg * 4);
            const uint32_t c1 = (uint32_t)(((2 * kk + 1) ^ g) * 16 + tg * 4);
            uint32_t a[4][4], b[4][2];
            #pragma unroll
            for (int mt = 0; mt < 4; mt++) {
                const uint32_t r0 = aBase + (uint32_t)((wm + mt * 16 + g) * 128);
                asm volatile("ld.shared.b32 %0,[%1];" : "=r"(a[mt][0]) : "r"(r0 + c0));
                asm volatile("ld.shared.b32 %0,[%1];" : "=r"(a[mt][1]) : "r"(r0 + 1024 + c0));
                asm volatile("ld.shared.b32 %0,[%1];" : "=r"(a[mt][2]) : "r"(r0 + c1));
                asm volatile("ld.shared.b32 %0,[%1];" : "=r"(a[mt][3]) : "r"(r0 + 1024 + c1));
            }
            #pragma unroll
            for (int nt = 0; nt < 4; nt++) {
                const uint32_t rb = bBase + (uint32_t)((wn + nt * 8 + g) * 128);
                asm volatile("ld.shared.b32 %0,[%1];" : "=r"(b[nt][0]) : "r"(rb + c0));
                asm volatile("ld.shared.b32 %0,[%1];" : "=r"(b[nt][1]) : "r"(rb + c1));
            }
            #pragma unroll
            for (int mt = 0; mt < 4; mt++)
                #pragma unroll
                for (int nt = 0; nt < 4; nt++)
                    mma_tf32(acc[mt][nt], a[mt], b[nt]);
        }
        __syncthreads();
    }

    #pragma unroll
    for (int mt = 0; mt < 4; mt++) {
        const int row0 = by * 128 + wm + mt * 16 + g;
        #pragma unroll
        for (int half = 0; half < 2; half++) {
            const int row = row0 + half * 8;
            float* Cr = C + (size_t)row * N;
            const float* Rr = RES ? (res + (size_t)row * N) : (const float*)0;
            #pragma unroll
            for (int nt = 0; nt < 4; nt++) {
                const int col = bx * 128 + wn + nt * 8 + tg * 2;
                float v0 = acc[mt][nt][half * 2 + 0];
                float v1 = acc[mt][nt][half * 2 + 1];
                if (BIAS) { v0 += bias[col]; v1 += bias[col + 1]; }
                if (GELU) {
                    v0 = 0.5f * v0 * (1.f + erff(v0 * 0.70710678118654752f));
                    v1 = 0.5f * v1 * (1.f + erff(v1 * 0.70710678118654752f));
                    v0 = f2tf32f(v0);
                    v1 = f2tf32f(v1);
                }
                if (RES) { v0 += Rr[col]; v1 += Rr[col + 1]; }
                float2 o; o.x = v0; o.y = v1;
                *(float2*)(Cr + col) = o;
            }
        }
    }
}

// ---------------------------------------------------------------------------
// Flash attention on mma.sync tf32.
// Grid (SEQ/128, NH, B), 256 threads (8 warps x 16 q-rows).
// SMEM: Q[128x64] | K 3x[32x64] | V 3x[32x64] | P[128x32]  (96KB)
// ---------------------------------------------------------------------------
#define ATT_SMEM 98304
#define NKV      (SEQ / 32)

__global__ __launch_bounds__(256, 2) void fattn(
    const float* __restrict__ qkv, float* __restrict__ out)
{
    extern __shared__ __align__(1024) char sm[];
    const uint32_t sb = smem_u32(sm);
    const uint32_t QOFF = 0, KOFF = 32768, VOFF = 57344, POFF = 81920;

    const int tid = threadIdx.x, wid = tid >> 5, lane = tid & 31;
    const int g = lane >> 2, tg = lane & 3;
    const int wm = wid * 16;
    const int qb = blockIdx.x, h = blockIdx.y, b = blockIdx.z;
    const size_t tok0 = (size_t)b * SEQ + (size_t)qb * 128;
    const float* qbase = qkv + tok0 * (3 * DM) + h * DH;

    // issue Q: 128 rows x 64 floats = 2048 float4 chunks (8 per thread)
    #pragma unroll
    for (int t = 0; t < 8; t++) {
        int idx = tid + t * 256;
        int r = idx >> 4, j = (idx & 15) * 4;
        cp_async16(sb + QOFF + AXS(r, j), qbase + (size_t)r * (3 * DM) + j);
    }
    // kv tile: K = 32x64 -> 512 chunks over threads 0-127 (4 each); V likewise 128-255
    auto issue_kv = [&](int it) {
        const int buf = it % 3;
        const uint32_t base = sb + (tid < 128 ? KOFF : VOFF) + buf * 8192;
        const int seg = (tid < 128 ? DM : 2 * DM);
        #pragma unroll
        for (int t = 0; t < 4; t++) {
            const int chunk = (tid & 127) + t * 128;
            const int r = chunk >> 4, j = (chunk & 15) * 4;
            const float* src = qkv + ((size_t)b * SEQ + it * 32 + r) * (3 * DM)
                             + seg + h * DH + j;
            cp_async16(base + AXS(r, j), src);
        }
        CP_COMMIT();
    };
    issue_kv(0);   // group 0 = Q + kv0
    issue_kv(1);
    issue_kv(2);

    CP_WAIT(2);
    __syncthreads();

    // Q fragments -> registers
    uint32_t qf[8][4];
    #pragma unroll
    for (int kk = 0; kk < 8; kk++) {
        qf[kk][0] = *(const uint32_t*)(sm + QOFF + AXS(wm + g,     kk * 8 + tg));
        qf[kk][1] = *(const uint32_t*)(sm + QOFF + AXS(wm + g + 8, kk * 8 + tg));
        qf[kk][2] = *(const uint32_t*)(sm + QOFF + AXS(wm + g,     kk * 8 + tg + 4));
        qf[kk][3] = *(const uint32_t*)(sm + QOFF + AXS(wm + g + 8, kk * 8 + tg + 4));
    }

    float oa[8][4];
    #pragma unroll
    for (int i = 0; i < 8; i++)
        #pragma unroll
        for (int j = 0; j < 4; j++) oa[i][j] = 0.f;
    float m0 = -1e30f, m1 = -1e30f, l0 = 0.f, l1 = 0.f;

    for (int it = 0; it < NKV; it++) {
        if (it < NKV - 2)      { CP_WAIT(2); }
        else if (it == NKV - 2){ CP_WAIT(1); }
        else                   { CP_WAIT(0); }
        __syncthreads();

        const int buf = it % 3;
        const char* kbuf = sm + KOFF + buf * 8192;
        const char* vbuf = sm + VOFF + buf * 8192;

        // ---- S = Q @ K^T ----
        float sf[4][4];
        #pragma unroll
        for (int nt = 0; nt < 4; nt++)
            #pragma unroll
            for (int e = 0; e < 4; e++) sf[nt][e] = 0.f;

        #pragma unroll
        for (int kk = 0; kk < 8; kk++) {
            #pragma unroll
            for (int nt = 0; nt < 4; nt++) {
                uint32_t bfr[2];
                bfr[0] = *(const uint32_t*)(kbuf + AXS(nt * 8 + g, kk * 8 + tg));
                bfr[1] = *(const uint32_t*)(kbuf + AXS(nt * 8 + g, kk * 8 + tg + 4));
                mma_tf32(sf[nt], qf[kk], bfr);
            }
        }

        // ---- online softmax ----
        float mx0 = -1e30f, mx1 = -1e30f;
        #pragma unroll
        for (int nt = 0; nt < 4; nt++) {
            #pragma unroll
            for (int e = 0; e < 4; e++) sf[nt][e] *= 0.125f;
            mx0 = fmaxf(mx0, fmaxf(sf[nt][0], sf[nt][1]));
            mx1 = fmaxf(mx1, fmaxf(sf[nt][2], sf[nt][3]));
        }
        mx0 = fmaxf(mx0, __shfl_xor_sync(0xffffffffu, mx0, 1));
        mx0 = fmaxf(mx0, __shfl_xor_sync(0xffffffffu, mx0, 2));
        mx1 = fmaxf(mx1, __shfl_xor_sync(0xffffffffu, mx1, 1));
        mx1 = fmaxf(mx1, __shfl_xor_sync(0xffffffffu, mx1, 2));
        const float nm0 = fmaxf(m0, mx0), nm1 = fmaxf(m1, mx1);
        const float cr0 = __expf(m0 - nm0), cr1 = __expf(m1 - nm1);
        m0 = nm0; m1 = nm1;

        float ls0 = 0.f, ls1 = 0.f;
        #pragma unroll
        for (int nt = 0; nt < 4; nt++) {
            sf[nt][0] = __expf(sf[nt][0] - m0);
            sf[nt][1] = __expf(sf[nt][1] - m0);
            sf[nt][2] = __expf(sf[nt][2] - m1);
            sf[nt][3] = __expf(sf[nt][3] - m1);
            ls0 += sf[nt][0] + sf[nt][1];
            ls1 += sf[nt][2] + sf[nt][3];
        }
        ls0 += __shfl_xor_sync(0xffffffffu, ls0, 1);
        ls0 += __shfl_xor_sync(0xffffffffu, ls0, 2);
        ls1 += __shfl_xor_sync(0xffffffffu, ls1, 1);
        ls1 += __shfl_xor_sync(0xffffffffu, ls1, 2);
        l0 = l0 * cr0 + ls0;
        l1 = l1 * cr1 + ls1;

        #pragma unroll
        for (int nt = 0; nt < 8; nt++) {
            oa[nt][0] *= cr0; oa[nt][1] *= cr0;
            oa[nt][2] *= cr1; oa[nt][3] *= cr1;
        }

        // ---- P -> SMEM (warp-local reshape) ----
        #pragma unroll
        for (int nt = 0; nt < 4; nt++) {
            *(float2*)(sm + POFF + PXS(wm + g,     nt * 8 + 2 * tg)) =
                make_float2(sf[nt][0], sf[nt][1]);
            *(float2*)(sm + POFF + PXS(wm + g + 8, nt * 8 + 2 * tg)) =
                make_float2(sf[nt][2], sf[nt][3]);
        }
        __syncwarp();

        // ---- O += P @ V ----
        #pragma unroll
        for (int kk = 0; kk < 4; kk++) {
            uint32_t a[4];
            a[0] = *(const uint32_t*)(sm + POFF + PXS(wm + g,     kk * 8 + tg));
            a[1] = *(const uint32_t*)(sm + POFF + PXS(wm + g + 8, kk * 8 + tg));
            a[2] = *(const uint32_t*)(sm + POFF + PXS(wm + g,     kk * 8 + tg + 4));
            a[3] = *(const uint32_t*)(sm + POFF + PXS(wm + g + 8, kk * 8 + tg + 4));
            #pragma unroll
            for (int nt = 0; nt < 8; nt++) {
                uint32_t bfr[2];
                bfr[0] = *(const uint32_t*)(vbuf + AXS(kk * 8 + tg,     nt * 8 + g));
                bfr[1] = *(const uint32_t*)(vbuf + AXS(kk * 8 + tg + 4, nt * 8 + g));
                mma_tf32(oa[nt], a, bfr);
            }
        }
        __syncthreads();
        if (it + 3 < NKV) issue_kv(it + 3);
    }

    // ---- epilogue ----
    const float inv0 = 1.f / l0, inv1 = 1.f / l1;
    #pragma unroll
    for (int nt = 0; nt < 8; nt++) {
        const int col = h * DH + nt * 8 + 2 * tg;
        float* o0 = out + (tok0 + wm + g) * DM + col;
        float* o1 = out + (tok0 + wm + g + 8) * DM + col;
        *(float2*)o0 = make_float2(f2tf32f(oa[nt][0] * inv0), f2tf32f(oa[nt][1] * inv0));
        *(float2*)o1 = make_float2(f2tf32f(oa[nt][2] * inv1), f2tf32f(oa[nt][3] * inv1));
    }
}

// ---------------------------------------------------------------------------
// Weight transpose + tf32 rounding
// ---------------------------------------------------------------------------
__global__ __launch_bounds__(256) void transpose_tf32(
    const float* __restrict__ W, float* __restrict__ Wt, int K, int N)
{
    __shared__ float t[32][33];
    int n0 = blockIdx.x * 32, k0 = blockIdx.y * 32;
    int tx = threadIdx.x & 31, ty = threadIdx.x >> 5;
    #pragma unroll
    for (int i = 0; i < 32; i += 8)
        t[ty + i][tx] = W[(size_t)(k0 + ty + i) * N + n0 + tx];
    __syncthreads();
    #pragma unroll
    for (int i = 0; i < 32; i += 8)
        Wt[(size_t)(n0 + ty + i) * K + k0 + tx] = f2tf32f(t[tx][ty + i]);
}

// ---------------------------------------------------------------------------
// silu / adaln
// ---------------------------------------------------------------------------
__global__ void silu_kernel(const float* __restrict__ in, float* __restrict__ out, int n4) {
    int i = blockIdx.x * blockDim.x + threadIdx.x;
    if (i >= n4) return;
    float4 v = ((const float4*)in)[i];
    v.x = f2tf32f(v.x / (1.f + expf(-v.x)));
    v.y = f2tf32f(v.y / (1.f + expf(-v.y)));
    v.z = f2tf32f(v.z / (1.f + expf(-v.z)));
    v.w = f2tf32f(v.w / (1.f + expf(-v.w)));
    ((float4*)out)[i] = v;
}

__global__ __launch_bounds__(256) void adaln_kernel(
    const float* __restrict__ x, const float* __restrict__ gb, float* __restrict__ out)
{
    int row = blockIdx.x;
    const float* xr = x + (size_t)row * DM;
    int i = threadIdx.x * 4;
    float4 v = *(const float4*)(xr + i);
    float s  = v.x + v.y + v.z + v.w;
    float ss = v.x*v.x + v.y*v.y + v.z*v.z + v.w*v.w;
    #pragma unroll
    for (int o = 16; o > 0; o >>= 1) {
        s  += __shfl_xor_sync(0xffffffffu, s,  o);
        ss += __shfl_xor_sync(0xffffffffu, ss, o);
    }
    __shared__ float sh[16];
    int w = threadIdx.x >> 5, ln = threadIdx.x & 31;
    if (ln == 0) { sh[w] = s; sh[w + 8] = ss; }
    __syncthreads();
    float fs = 0.f, fss = 0.f;
    #pragma unroll
    for (int k = 0; k < 8; k++) { fs += sh[k]; fss += sh[k + 8]; }
    float mu   = fs  * (1.f / DM);
    float var  = fss * (1.f / DM) - mu * mu;
    float rstd = rsqrtf(var + 1e-5f);

    const float* gp = gb + (size_t)row * (2 * DM);
    float4 ga = *(const float4*)(gp + i);
    float4 be = *(const float4*)(gp + DM + i);
    float4 o;
    o.x = f2tf32f((v.x - mu) * rstd * (1.f + ga.x) + be.x);
    o.y = f2tf32f((v.y - mu) * rstd * (1.f + ga.y) + be.y);
    o.z = f2tf32f((v.z - mu) * rstd * (1.f + ga.z) + be.z);
    o.w = f2tf32f((v.w - mu) * rstd * (1.f + ga.w) + be.w);
    *(float4*)(out + (size_t)row * DM + i) = o;
}

// ---------------------------------------------------------------------------
// Launch
// ---------------------------------------------------------------------------
extern "C" void kernel_launch(void* const* d_in, const int* in_sizes, int n_in,
                              void* d_out, int out_size)
{
    const float* x          = (const float*)d_in[0];
    const float* cond       = (const float*)d_in[1];
    const float* p1_w       = (const float*)d_in[2];
    const float* p1_b       = (const float*)d_in[3];
    const float* qkv_w      = (const float*)d_in[4];
    const float* attn_out_w = (const float*)d_in[5];
    const float* p2_w       = (const float*)d_in[6];
    const float* p2_b       = (const float*)d_in[7];
    const float* ffn_w1     = (const float*)d_in[8];
    const float* ffn_b1     = (const float*)d_in[9];
    const float* ffn_w2     = (const float*)d_in[10];
    const float* ffn_b2     = (const float*)d_in[11];
    float* out = (float*)d_out;

    float *sc, *gb, *h, *qkv, *attn, *x2, *ff;
    float *wt_p1, *wt_qkv, *wt_ao, *wt_p2, *wt_f1, *wt_f2;
    cudaGetSymbolAddress((void**)&sc,    g_sc);
    cudaGetSymbolAddress((void**)&gb,    g_gb);
    cudaGetSymbolAddress((void**)&h,     g_h);
    cudaGetSymbolAddress((void**)&qkv,   g_qkv);
    cudaGetSymbolAddress((void**)&attn,  g_attn);
    cudaGetSymbolAddress((void**)&x2,    g_x2);
    cudaGetSymbolAddress((void**)&ff,    g_ff);
    cudaGetSymbolAddress((void**)&wt_p1,  g_wt_p1);
    cudaGetSymbolAddress((void**)&wt_qkv, g_wt_qkv);
    cudaGetSymbolAddress((void**)&wt_ao,  g_wt_ao);
    cudaGetSymbolAddress((void**)&wt_p2,  g_wt_p2);
    cudaGetSymbolAddress((void**)&wt_f1,  g_wt_f1);
    cudaGetSymbolAddress((void**)&wt_f2,  g_wt_f2);

    cudaFuncSetAttribute(tgemm<1,0,0>, cudaFuncAttributeMaxDynamicSharedMemorySize, TG_SMEM);
    cudaFuncSetAttribute(tgemm<0,0,0>, cudaFuncAttributeMaxDynamicSharedMemorySize, TG_SMEM);
    cudaFuncSetAttribute(tgemm<0,0,1>, cudaFuncAttributeMaxDynamicSharedMemorySize, TG_SMEM);
    cudaFuncSetAttribute(tgemm<1,1,0>, cudaFuncAttributeMaxDynamicSharedMemorySize, TG_SMEM);
    cudaFuncSetAttribute(tgemm<1,0,1>, cudaFuncAttributeMaxDynamicSharedMemorySize, TG_SMEM);
    cudaFuncSetAttribute(fattn, cudaFuncAttributeMaxDynamicSharedMemorySize, ATT_SMEM);

    transpose_tf32<<<dim3(2048/32,  512/32), 256>>>(p1_w,       wt_p1,  512,  2048);
    transpose_tf32<<<dim3(3072/32, 1024/32), 256>>>(qkv_w,      wt_qkv, 1024, 3072);
    transpose_tf32<<<dim3(1024/32, 1024/32), 256>>>(attn_out_w, wt_ao,  1024, 1024);
    transpose_tf32<<<dim3(2048/32,  512/32), 256>>>(p2_w,       wt_p2,  512,  2048);
    transpose_tf32<<<dim3(4096/32, 1024/32), 256>>>(ffn_w1,     wt_f1,  1024, 4096);
    transpose_tf32<<<dim3(1024/32, 4096/32), 256>>>(ffn_w2,     wt_f2,  4096, 1024);

    silu_kernel<<<(BS_TOK * DC / 4 + 255) / 256, 256>>>(cond, sc, BS_TOK * DC / 4);
    tgemm<1,0,0><<<dim3(2048/128, BS_TOK/128), 256, TG_SMEM>>>(
        sc, wt_p1, p1_b, nullptr, gb, BS_TOK, 2048, DC);
    adaln_kernel<<<BS_TOK, 256>>>(x, gb, h);
    tgemm<0,0,0><<<dim3(3072/128, BS_TOK/128), 256, TG_SMEM>>>(
        h, wt_qkv, nullptr, nullptr, qkv, BS_TOK, 3072, DM);
    fattn<<<dim3(SEQ/128, NH, 2), 256, ATT_SMEM>>>(qkv, attn);
    tgemm<0,0,1><<<dim3(1024/128, BS_TOK/128), 256, TG_SMEM>>>(
        attn, wt_ao, nullptr, x, x2, BS_TOK, 1024, DM);
    tgemm<1,0,0><<<dim3(2048/128, BS_TOK/128), 256, TG_SMEM>>>(
        sc, wt_p2, p2_b, nullptr, gb, BS_TOK, 2048, DC);
    adaln_kernel<<<BS_TOK, 256>>>(x2, gb, h);
    tgemm<1,1,0><<<dim3(DFF/128, BS_TOK/128), 256, TG_SMEM>>>(
        h, wt_f1, ffn_b1, nullptr, ff, BS_TOK, DFF, DM);
    tgemm<1,0,1><<<dim3(1024/128, BS_TOK/128), 256, TG_SMEM>>>(
        ff, wt_f2, ffn_b2, x2, out, BS_TOK, 1024, DFF);
}

// round 7
// speedup vs baseline: 5.8006x; 1.6177x over previous
#include <cuda_runtime.h>
#include <cuda_fp16.h>
#include <math.h>
#include <stdint.h>

// ---------------------------------------------------------------------------
// DecoderBlock: B=2, S=2048, D_MODEL=1024, D_COND=512, H=16, d=64, FF=4096
// Round 6: fp16 m16n8k16 GEMMs with ldmatrix (same 10-bit mantissa as tf32,
// 2x tensor rate, half the traffic). Attention stays tf32, outputs fp16.
// ---------------------------------------------------------------------------

#define BS_TOK   4096
#define DM       1024
#define DC       512
#define DFF      4096
#define NH       16
#define DH       64
#define SEQ      2048

// ---------------- scratch ---------------------------------------------------
__device__ __half g_sc  [BS_TOK * DC];       // silu(cond), fp16
__device__ float  g_gb  [BS_TOK * 2 * DM];   // gamma/beta
__device__ __half g_h   [BS_TOK * DM];       // adaln out, fp16
__device__ float  g_qkv [BS_TOK * 3 * DM];   // qkv (attention reads fp32)
__device__ __half g_attn[BS_TOK * DM];       // attention out, fp16
__device__ float  g_x2  [BS_TOK * DM];       // residual stream
__device__ __half g_ff  [BS_TOK * DFF];      // gelu out, fp16
// fp16 transposed weights [N,K]
__device__ __half g_wt_p1 [2 * DM * DC];
__device__ __half g_wt_qkv[3 * DM * DM];
__device__ __half g_wt_ao [DM * DM];
__device__ __half g_wt_p2 [2 * DM * DC];
__device__ __half g_wt_f1 [DFF * DM];
__device__ __half g_wt_f2 [DM * DFF];

// ---------------- helpers ---------------------------------------------------
__device__ __forceinline__ uint32_t smem_u32(const void* p) {
    uint32_t a;
    asm("{ .reg .u64 t; cvta.to.shared.u64 t, %1; cvt.u32.u64 %0, t; }"
        : "=r"(a) : "l"(p));
    return a;
}
__device__ __forceinline__ void cp_async16(uint32_t dst, const void* src) {
    asm volatile("cp.async.cg.shared.global [%0], [%1], 16;"
                 :: "r"(dst), "l"(src) : "memory");
}
#define CP_COMMIT() asm volatile("cp.async.commit_group;" ::: "memory")
#define CP_WAIT(n)  asm volatile("cp.async.wait_group %0;" :: "n"(n) : "memory")

__device__ __forceinline__ void mma_f16(float* c, const uint32_t* a, const uint32_t* b) {
    asm volatile("mma.sync.aligned.m16n8k16.row.col.f32.f16.f16.f32 "
        "{%0,%1,%2,%3}, {%4,%5,%6,%7}, {%8,%9}, {%0,%1,%2,%3};"
        : "+f"(c[0]), "+f"(c[1]), "+f"(c[2]), "+f"(c[3])
        : "r"(a[0]), "r"(a[1]), "r"(a[2]), "r"(a[3]), "r"(b[0]), "r"(b[1]));
}
__device__ __forceinline__ void mma_tf32(float* c, const uint32_t* a, const uint32_t* b) {
    asm volatile("mma.sync.aligned.m16n8k8.row.col.f32.tf32.tf32.f32 "
        "{%0,%1,%2,%3}, {%4,%5,%6,%7}, {%8,%9}, {%0,%1,%2,%3};"
        : "+f"(c[0]), "+f"(c[1]), "+f"(c[2]), "+f"(c[3])
        : "r"(a[0]), "r"(a[1]), "r"(a[2]), "r"(a[3]), "r"(b[0]), "r"(b[1]));
}
#define LDMX4(r0, r1, r2, r3, addr)                                           \
    asm volatile("ldmatrix.sync.aligned.m8n8.x4.shared.b16 {%0,%1,%2,%3}, [%4];" \
        : "=r"(r0), "=r"(r1), "=r"(r2), "=r"(r3) : "r"(addr))

// fp16 smem tile: rows of 64 halves = 128B. 16B chunk c (0..7) of row r:
#define HXS(r, c) ((uint32_t)((r) * 128 + (((c) ^ ((r) & 7)) << 4)))
// fp32 attention smem (64 floats/row = 256B), float-col granularity
#define AXS(r, c) ((uint32_t)((r) * 256 + ((((c) ^ ((((r) & 7)) << 2))) << 2)))
#define PXS(r, c) ((uint32_t)((r) * 128 + ((((c) ^ ((((r) & 7)) << 2))) << 2)))

// ---------------------------------------------------------------------------
// fp16 mma GEMM: C[M,N] = A[M,K] @ Bt[N,K]^T (+bias)(+gelu)(+res)
// BM=BN=128, BK=64, 3-stage cp.async, 256 threads, 8 warps (64x32 each).
// ---------------------------------------------------------------------------
#define TG_SMEM 98304   // 3 x (16KB A + 16KB B)

template<int BIAS, int GELU, int RES, int OUTH>
__global__ __launch_bounds__(256) void hgemm(
    const __half* __restrict__ A, const __half* __restrict__ Bt,
    const float* __restrict__ bias, const float* __restrict__ res,
    void* __restrict__ Cv, int M, int N, int K)
{
    extern __shared__ __align__(1024) char smem_raw[];
    const uint32_t sA = smem_u32(smem_raw);
    const uint32_t sB = sA + 3 * 16384;

    const int tid  = threadIdx.x;
    const int wid  = tid >> 5;
    const int lane = tid & 31;
    const int bx = blockIdx.x, by = blockIdx.y;

    const __half* Ab = A  + (size_t)(by * 128) * K;
    const __half* Bb = Bt + (size_t)(bx * 128) * K;
    const int S = K >> 6;   // BK=64 stages

    const int lr = tid >> 3;     // 0..31
    const int lc = tid & 7;      // chunk 0..7

    auto issue = [&](int s, int st) {
        const int k0 = s * 64;
        const uint32_t ao = sA + st * 16384;
        const uint32_t bo = sB + st * 16384;
        #pragma unroll
        for (int t = 0; t < 4; t++) {
            int r = lr + t * 32;
            uint32_t off = HXS(r, lc);
            cp_async16(ao + off, Ab + (size_t)r * K + k0 + lc * 8);
            cp_async16(bo + off, Bb + (size_t)r * K + k0 + lc * 8);
        }
        CP_COMMIT();
    };

    float acc[4][4][4];
    #pragma unroll
    for (int i = 0; i < 4; i++)
        #pragma unroll
        for (int j = 0; j < 4; j++)
            #pragma unroll
            for (int k = 0; k < 4; k++) acc[i][j][k] = 0.f;

    const int wm = (wid >> 2) * 64;
    const int wn = (wid & 3) * 32;
    const int g  = lane >> 2;
    const int tg = lane & 3;
    const int rr  = lane & 7;
    const int sub = lane >> 3;

    // ldmatrix address components (constant over stages)
    uint32_t aRowOff[4], aMask[4];
    const int khalfA = sub >> 1;
    #pragma unroll
    for (int mt = 0; mt < 4; mt++) {
        int row = wm + mt * 16 + (sub & 1) * 8 + rr;
        aRowOff[mt] = (uint32_t)(row * 128);
        aMask[mt]   = (uint32_t)(row & 7);
    }
    uint32_t bRowOff[2], bMask[2];
    const int khalfB = sub & 1;
    #pragma unroll
    for (int ntp = 0; ntp < 2; ntp++) {
        int row = wn + (ntp * 2 + (sub >> 1)) * 8 + rr;
        bRowOff[ntp] = (uint32_t)(row * 128);
        bMask[ntp]   = (uint32_t)(row & 7);
    }

    issue(0, 0);
    issue(1, 1);

    for (int s = 0; s < S; s++) {
        if (s + 1 < S) { CP_WAIT(1); } else { CP_WAIT(0); }
        __syncthreads();
        if (s + 2 < S) issue(s + 2, (s + 2) % 3);

        const uint32_t aBase = sA + (s % 3) * 16384;
        const uint32_t bBase = sB + (s % 3) * 16384;
        #pragma unroll
        for (int kk = 0; kk < 4; kk++) {   // k16 steps within BK=64
            uint32_t a[4][4], b[4][2];
            #pragma unroll
            for (int mt = 0; mt < 4; mt++) {
                uint32_t addr = aBase + aRowOff[mt]
                              + (((uint32_t)(kk * 2 + khalfA) ^ aMask[mt]) << 4);
                LDMX4(a[mt][0], a[mt][1], a[mt][2], a[mt][3], addr);
            }
            #pragma unroll
            for (int ntp = 0; ntp < 2; ntp++) {
                uint32_t addr = bBase + bRowOff[ntp]
                              + (((uint32_t)(kk * 2 + khalfB) ^ bMask[ntp]) << 4);
                LDMX4(b[ntp * 2][0], b[ntp * 2][1], b[ntp * 2 + 1][0], b[ntp * 2 + 1][1], addr);
            }
            #pragma unroll
            for (int mt = 0; mt < 4; mt++)
                #pragma unroll
                for (int nt = 0; nt < 4; nt++)
                    mma_f16(acc[mt][nt], a[mt], b[nt]);
        }
        __syncthreads();
    }

    // ---- epilogue ----
    #pragma unroll
    for (int mt = 0; mt < 4; mt++) {
        #pragma unroll
        for (int hh = 0; hh < 2; hh++) {
            const int row = by * 128 + wm + mt * 16 + g + hh * 8;
            const float* Rr = RES ? (res + (size_t)row * N) : (const float*)0;
            #pragma unroll
            for (int nt = 0; nt < 4; nt++) {
                const int col = bx * 128 + wn + nt * 8 + tg * 2;
                float v0 = acc[mt][nt][hh * 2 + 0];
                float v1 = acc[mt][nt][hh * 2 + 1];
                if (BIAS) { v0 += bias[col]; v1 += bias[col + 1]; }
                if (GELU) {
                    v0 = 0.5f * v0 * (1.f + erff(v0 * 0.70710678118654752f));
                    v1 = 0.5f * v1 * (1.f + erff(v1 * 0.70710678118654752f));
                }
                if (RES) { v0 += Rr[col]; v1 += Rr[col + 1]; }
                if (OUTH) {
                    __half2* Ch = (__half2*)((__half*)Cv + (size_t)row * N + col);
                    *Ch = __floats2half2_rn(v0, v1);
                } else {
                    float2* Cf = (float2*)((float*)Cv + (size_t)row * N + col);
                    *Cf = make_float2(v0, v1);
                }
            }
        }
    }
}

// ---------------------------------------------------------------------------
// Flash attention (tf32 mma, fp32 qkv input, fp16 output).
// ---------------------------------------------------------------------------
#define ATT_SMEM 98304
#define NKV      (SEQ / 32)

__global__ __launch_bounds__(256, 2) void fattn(
    const float* __restrict__ qkv, __half* __restrict__ out)
{
    extern __shared__ __align__(1024) char sm[];
    const uint32_t sb = smem_u32(sm);
    const uint32_t QOFF = 0, KOFF = 32768, VOFF = 57344, POFF = 81920;

    const int tid = threadIdx.x, wid = tid >> 5, lane = tid & 31;
    const int g = lane >> 2, tg = lane & 3;
    const int wm = wid * 16;
    const int qb = blockIdx.x, h = blockIdx.y, b = blockIdx.z;
    const size_t tok0 = (size_t)b * SEQ + (size_t)qb * 128;
    const float* qbase = qkv + tok0 * (3 * DM) + h * DH;

    #pragma unroll
    for (int t = 0; t < 8; t++) {
        int idx = tid + t * 256;
        int r = idx >> 4, j = (idx & 15) * 4;
        cp_async16(sb + QOFF + AXS(r, j), qbase + (size_t)r * (3 * DM) + j);
    }
    auto issue_kv = [&](int it) {
        const int buf = it % 3;
        const uint32_t base = sb + (tid < 128 ? KOFF : VOFF) + buf * 8192;
        const int seg = (tid < 128 ? DM : 2 * DM);
        #pragma unroll
        for (int t = 0; t < 4; t++) {
            const int chunk = (tid & 127) + t * 128;
            const int r = chunk >> 4, j = (chunk & 15) * 4;
            const float* src = qkv + ((size_t)b * SEQ + it * 32 + r) * (3 * DM)
                             + seg + h * DH + j;
            cp_async16(base + AXS(r, j), src);
        }
        CP_COMMIT();
    };
    issue_kv(0);
    issue_kv(1);
    issue_kv(2);

    CP_WAIT(2);
    __syncthreads();

    uint32_t qf[8][4];
    #pragma unroll
    for (int kk = 0; kk < 8; kk++) {
        qf[kk][0] = *(const uint32_t*)(sm + QOFF + AXS(wm + g,     kk * 8 + tg));
        qf[kk][1] = *(const uint32_t*)(sm + QOFF + AXS(wm + g + 8, kk * 8 + tg));
        qf[kk][2] = *(const uint32_t*)(sm + QOFF + AXS(wm + g,     kk * 8 + tg + 4));
        qf[kk][3] = *(const uint32_t*)(sm + QOFF + AXS(wm + g + 8, kk * 8 + tg + 4));
    }

    float oa[8][4];
    #pragma unroll
    for (int i = 0; i < 8; i++)
        #pragma unroll
        for (int j = 0; j < 4; j++) oa[i][j] = 0.f;
    float m0 = -1e30f, m1 = -1e30f, l0 = 0.f, l1 = 0.f;

    for (int it = 0; it < NKV; it++) {
        if (it < NKV - 2)      { CP_WAIT(2); }
        else if (it == NKV - 2){ CP_WAIT(1); }
        else                   { CP_WAIT(0); }
        __syncthreads();

        const int buf = it % 3;
        const char* kbuf = sm + KOFF + buf * 8192;
        const char* vbuf = sm + VOFF + buf * 8192;

        float sf[4][4];
        #pragma unroll
        for (int nt = 0; nt < 4; nt++)
            #pragma unroll
            for (int e = 0; e < 4; e++) sf[nt][e] = 0.f;

        #pragma unroll
        for (int kk = 0; kk < 8; kk++) {
            #pragma unroll
            for (int nt = 0; nt < 4; nt++) {
                uint32_t bfr[2];
                bfr[0] = *(const uint32_t*)(kbuf + AXS(nt * 8 + g, kk * 8 + tg));
                bfr[1] = *(const uint32_t*)(kbuf + AXS(nt * 8 + g, kk * 8 + tg + 4));
                mma_tf32(sf[nt], qf[kk], bfr);
            }
        }

        float mx0 = -1e30f, mx1 = -1e30f;
        #pragma unroll
        for (int nt = 0; nt < 4; nt++) {
            #pragma unroll
            for (int e = 0; e < 4; e++) sf[nt][e] *= 0.125f;
            mx0 = fmaxf(mx0, fmaxf(sf[nt][0], sf[nt][1]));
            mx1 = fmaxf(mx1, fmaxf(sf[nt][2], sf[nt][3]));
        }
        mx0 = fmaxf(mx0, __shfl_xor_sync(0xffffffffu, mx0, 1));
        mx0 = fmaxf(mx0, __shfl_xor_sync(0xffffffffu, mx0, 2));
        mx1 = fmaxf(mx1, __shfl_xor_sync(0xffffffffu, mx1, 1));
        mx1 = fmaxf(mx1, __shfl_xor_sync(0xffffffffu, mx1, 2));
        const float nm0 = fmaxf(m0, mx0), nm1 = fmaxf(m1, mx1);
        const float cr0 = __expf(m0 - nm0), cr1 = __expf(m1 - nm1);
        m0 = nm0; m1 = nm1;

        float ls0 = 0.f, ls1 = 0.f;
        #pragma unroll
        for (int nt = 0; nt < 4; nt++) {
            sf[nt][0] = __expf(sf[nt][0] - m0);
            sf[nt][1] = __expf(sf[nt][1] - m0);
            sf[nt][2] = __expf(sf[nt][2] - m1);
            sf[nt][3] = __expf(sf[nt][3] - m1);
            ls0 += sf[nt][0] + sf[nt][1];
            ls1 += sf[nt][2] + sf[nt][3];
        }
        ls0 += __shfl_xor_sync(0xffffffffu, ls0, 1);
        ls0 += __shfl_xor_sync(0xffffffffu, ls0, 2);
        ls1 += __shfl_xor_sync(0xffffffffu, ls1, 1);
        ls1 += __shfl_xor_sync(0xffffffffu, ls1, 2);
        l0 = l0 * cr0 + ls0;
        l1 = l1 * cr1 + ls1;

        #pragma unroll
        for (int nt = 0; nt < 8; nt++) {
            oa[nt][0] *= cr0; oa[nt][1] *= cr0;
            oa[nt][2] *= cr1; oa[nt][3] *= cr1;
        }

        #pragma unroll
        for (int nt = 0; nt < 4; nt++) {
            *(float2*)(sm + POFF + PXS(wm + g,     nt * 8 + 2 * tg)) =
                make_float2(sf[nt][0], sf[nt][1]);
            *(float2*)(sm + POFF + PXS(wm + g + 8, nt * 8 + 2 * tg)) =
                make_float2(sf[nt][2], sf[nt][3]);
        }
        __syncwarp();

        #pragma unroll
        for (int kk = 0; kk < 4; kk++) {
            uint32_t a[4];
            a[0] = *(const uint32_t*)(sm + POFF + PXS(wm + g,     kk * 8 + tg));
            a[1] = *(const uint32_t*)(sm + POFF + PXS(wm + g + 8, kk * 8 + tg));
            a[2] = *(const uint32_t*)(sm + POFF + PXS(wm + g,     kk * 8 + tg + 4));
            a[3] = *(const uint32_t*)(sm + POFF + PXS(wm + g + 8, kk * 8 + tg + 4));
            #pragma unroll
            for (int nt = 0; nt < 8; nt++) {
                uint32_t bfr[2];
                bfr[0] = *(const uint32_t*)(vbuf + AXS(kk * 8 + tg,     nt * 8 + g));
                bfr[1] = *(const uint32_t*)(vbuf + AXS(kk * 8 + tg + 4, nt * 8 + g));
                mma_tf32(oa[nt], a, bfr);
            }
        }
        __syncthreads();
        if (it + 3 < NKV) issue_kv(it + 3);
    }

    const float inv0 = 1.f / l0, inv1 = 1.f / l1;
    #pragma unroll
    for (int nt = 0; nt < 8; nt++) {
        const int col = h * DH + nt * 8 + 2 * tg;
        __half* o0 = out + (tok0 + wm + g) * DM + col;
        __half* o1 = out + (tok0 + wm + g + 8) * DM + col;
        *(__half2*)o0 = __floats2half2_rn(oa[nt][0] * inv0, oa[nt][1] * inv0);
        *(__half2*)o1 = __floats2half2_rn(oa[nt][2] * inv1, oa[nt][3] * inv1);
    }
}

// ---------------------------------------------------------------------------
// Weight transpose to fp16: Wt[n,k] = half(W[k,n])
// ---------------------------------------------------------------------------
__global__ __launch_bounds__(256) void transpose_h(
    const float* __restrict__ W, __half* __restrict__ Wt, int K, int N)
{
    __shared__ float t[32][33];
    int n0 = blockIdx.x * 32, k0 = blockIdx.y * 32;
    int tx = threadIdx.x & 31, ty = threadIdx.x >> 5;
    #pragma unroll
    for (int i = 0; i < 32; i += 8)
        t[ty + i][tx] = W[(size_t)(k0 + ty + i) * N + n0 + tx];
    __syncthreads();
    #pragma unroll
    for (int i = 0; i < 32; i += 8)
        Wt[(size_t)(n0 + ty + i) * K + k0 + tx] = __float2half_rn(t[tx][ty + i]);
}

// ---------------------------------------------------------------------------
// silu -> fp16
// ---------------------------------------------------------------------------
__global__ void silu_kernel(const float* __restrict__ in, __half* __restrict__ out, int n4) {
    int i = blockIdx.x * blockDim.x + threadIdx.x;
    if (i >= n4) return;
    float4 v = ((const float4*)in)[i];
    __half2 a = __floats2half2_rn(v.x / (1.f + expf(-v.x)), v.y / (1.f + expf(-v.y)));
    __half2 b = __floats2half2_rn(v.z / (1.f + expf(-v.z)), v.w / (1.f + expf(-v.w)));
    __half2* o = (__half2*)(out + (size_t)i * 4);
    o[0] = a; o[1] = b;
}

// ---------------------------------------------------------------------------
// AdaLN -> fp16
// ---------------------------------------------------------------------------
__global__ __launch_bounds__(256) void adaln_kernel(
    const float* __restrict__ x, const float* __restrict__ gb, __half* __restrict__ out)
{
    int row = blockIdx.x;
    const float* xr = x + (size_t)row * DM;
    int i = threadIdx.x * 4;
    float4 v = *(const float4*)(xr + i);
    float s  = v.x + v.y + v.z + v.w;
    float ss = v.x*v.x + v.y*v.y + v.z*v.z + v.w*v.w;
    #pragma unroll
    for (int o = 16; o > 0; o >>= 1) {
        s  += __shfl_xor_sync(0xffffffffu, s,  o);
        ss += __shfl_xor_sync(0xffffffffu, ss, o);
    }
    __shared__ float sh[16];
    int w = threadIdx.x >> 5, ln = threadIdx.x & 31;
    if (ln == 0) { sh[w] = s; sh[w + 8] = ss; }
    __syncthreads();
    float fs = 0.f, fss = 0.f;
    #pragma unroll
    for (int k = 0; k < 8; k++) { fs += sh[k]; fss += sh[k + 8]; }
    float mu   = fs  * (1.f / DM);
    float var  = fss * (1.f / DM) - mu * mu;
    float rstd = rsqrtf(var + 1e-5f);

    const float* gp = gb + (size_t)row * (2 * DM);
    float4 ga = *(const float4*)(gp + i);
    float4 be = *(const float4*)(gp + DM + i);
    float o0 = (v.x - mu) * rstd * (1.f + ga.x) + be.x;
    float o1 = (v.y - mu) * rstd * (1.f + ga.y) + be.y;
    float o2 = (v.z - mu) * rstd * (1.f + ga.z) + be.z;
    float o3 = (v.w - mu) * rstd * (1.f + ga.w) + be.w;
    __half2* op = (__half2*)(out + (size_t)row * DM + i);
    op[0] = __floats2half2_rn(o0, o1);
    op[1] = __floats2half2_rn(o2, o3);
}

// ---------------------------------------------------------------------------
// Launch
// ---------------------------------------------------------------------------
extern "C" void kernel_launch(void* const* d_in, const int* in_sizes, int n_in,
                              void* d_out, int out_size)
{
    const float* x          = (const float*)d_in[0];
    const float* cond       = (const float*)d_in[1];
    const float* p1_w       = (const float*)d_in[2];
    const float* p1_b       = (const float*)d_in[3];
    const float* qkv_w      = (const float*)d_in[4];
    const float* attn_out_w = (const float*)d_in[5];
    const float* p2_w       = (const float*)d_in[6];
    const float* p2_b       = (const float*)d_in[7];
    const float* ffn_w1     = (const float*)d_in[8];
    const float* ffn_b1     = (const float*)d_in[9];
    const float* ffn_w2     = (const float*)d_in[10];
    const float* ffn_b2     = (const float*)d_in[11];
    float* out = (float*)d_out;

    __half *sc, *h, *attn, *ff;
    float *gb, *qkv, *x2;
    __half *wt_p1, *wt_qkv, *wt_ao, *wt_p2, *wt_f1, *wt_f2;
    cudaGetSymbolAddress((void**)&sc,    g_sc);
    cudaGetSymbolAddress((void**)&gb,    g_gb);
    cudaGetSymbolAddress((void**)&h,     g_h);
    cudaGetSymbolAddress((void**)&qkv,   g_qkv);
    cudaGetSymbolAddress((void**)&attn,  g_attn);
    cudaGetSymbolAddress((void**)&x2,    g_x2);
    cudaGetSymbolAddress((void**)&ff,    g_ff);
    cudaGetSymbolAddress((void**)&wt_p1,  g_wt_p1);
    cudaGetSymbolAddress((void**)&wt_qkv, g_wt_qkv);
    cudaGetSymbolAddress((void**)&wt_ao,  g_wt_ao);
    cudaGetSymbolAddress((void**)&wt_p2,  g_wt_p2);
    cudaGetSymbolAddress((void**)&wt_f1,  g_wt_f1);
    cudaGetSymbolAddress((void**)&wt_f2,  g_wt_f2);

    cudaFuncSetAttribute(hgemm<1,0,0,0>, cudaFuncAttributeMaxDynamicSharedMemorySize, TG_SMEM);
    cudaFuncSetAttribute(hgemm<0,0,0,0>, cudaFuncAttributeMaxDynamicSharedMemorySize, TG_SMEM);
    cudaFuncSetAttribute(hgemm<0,0,1,0>, cudaFuncAttributeMaxDynamicSharedMemorySize, TG_SMEM);
    cudaFuncSetAttribute(hgemm<1,1,0,1>, cudaFuncAttributeMaxDynamicSharedMemorySize, TG_SMEM);
    cudaFuncSetAttribute(hgemm<1,0,1,0>, cudaFuncAttributeMaxDynamicSharedMemorySize, TG_SMEM);
    cudaFuncSetAttribute(fattn, cudaFuncAttributeMaxDynamicSharedMemorySize, ATT_SMEM);

    // Weight transposes ([K,N] fp32 -> [N,K] fp16)
    transpose_h<<<dim3(2048/32,  512/32), 256>>>(p1_w,       wt_p1,  512,  2048);
    transpose_h<<<dim3(3072/32, 1024/32), 256>>>(qkv_w,      wt_qkv, 1024, 3072);
    transpose_h<<<dim3(1024/32, 1024/32), 256>>>(attn_out_w, wt_ao,  1024, 1024);
    transpose_h<<<dim3(2048/32,  512/32), 256>>>(p2_w,       wt_p2,  512,  2048);
    transpose_h<<<dim3(4096/32, 1024/32), 256>>>(ffn_w1,     wt_f1,  1024, 4096);
    transpose_h<<<dim3(1024/32, 4096/32), 256>>>(ffn_w2,     wt_f2,  4096, 1024);

    // 1. sc = silu(cond)  -> fp16
    silu_kernel<<<(BS_TOK * DC / 4 + 255) / 256, 256>>>(cond, sc, BS_TOK * DC / 4);
    // 2. gb = sc @ p1_w + p1_b  (fp32 out)
    hgemm<1,0,0,0><<<dim3(2048/128, BS_TOK/128), 256, TG_SMEM>>>(
        sc, wt_p1, p1_b, nullptr, gb, BS_TOK, 2048, DC);
    // 3. h = adaln(x, gb) -> fp16
    adaln_kernel<<<BS_TOK, 256>>>(x, gb, h);
    // 4. qkv = h @ qkv_w  (fp32 out for attention)
    hgemm<0,0,0,0><<<dim3(3072/128, BS_TOK/128), 256, TG_SMEM>>>(
        h, wt_qkv, nullptr, nullptr, qkv, BS_TOK, 3072, DM);
    // 5. attention -> fp16
    fattn<<<dim3(SEQ/128, NH, 2), 256, ATT_SMEM>>>(qkv, attn);
    // 6. x2 = x + attn @ attn_out_w  (fp32 out)
    hgemm<0,0,1,0><<<dim3(1024/128, BS_TOK/128), 256, TG_SMEM>>>(
        attn, wt_ao, nullptr, x, x2, BS_TOK, 1024, DM);
    // 7. gb = sc @ p2_w + p2_b
    hgemm<1,0,0,0><<<dim3(2048/128, BS_TOK/128), 256, TG_SMEM>>>(
        sc, wt_p2, p2_b, nullptr, gb, BS_TOK, 2048, DC);
    // 8. h = adaln(x2, gb) -> fp16
    adaln_kernel<<<BS_TOK, 256>>>(x2, gb, h);
    // 9. ff = gelu(h @ ffn_w1 + ffn_b1) -> fp16
    hgemm<1,1,0,1><<<dim3(DFF/128, BS_TOK/128), 256, TG_SMEM>>>(
        h, wt_f1, ffn_b1, nullptr, ff, BS_TOK, DFF, DM);
    // 10. out = x2 + ff @ ffn_w2 + ffn_b2  (fp32 out)
    hgemm<1,0,1,0><<<dim3(1024/128, BS_TOK/128), 256, TG_SMEM>>>(
        ff, wt_f2, ffn_b2, x2, out, BS_TOK, 1024, DFF);
}

// round 10
// speedup vs baseline: 7.4773x; 1.2890x over previous
#include <cuda_runtime.h>
#include <cuda_fp16.h>
#include <math.h>
#include <stdint.h>

// ---------------------------------------------------------------------------
// DecoderBlock: B=2, S=2048, D_MODEL=1024, D_COND=512, H=16, d=64, FF=4096
// Round 8: fp16 flash-attention (m16n8k16, register-repacked P, ldmatrix.trans
// V). qkv buffer now fp16. GEMMs unchanged from round 7.
// ---------------------------------------------------------------------------

#define BS_TOK   4096
#define DM       1024
#define DC       512
#define DFF      4096
#define NH       16
#define DH       64
#define SEQ      2048

// ---------------- scratch ---------------------------------------------------
__device__ __half g_sc  [BS_TOK * DC];
__device__ float  g_gb  [BS_TOK * 2 * DM];
__device__ __half g_h   [BS_TOK * DM];
__device__ __half g_qkv [BS_TOK * 3 * DM];   // fp16 now
__device__ __half g_attn[BS_TOK * DM];
__device__ float  g_x2  [BS_TOK * DM];
__device__ __half g_ff  [BS_TOK * DFF];
__device__ __half g_wt_p1 [2 * DM * DC];
__device__ __half g_wt_qkv[3 * DM * DM];
__device__ __half g_wt_ao [DM * DM];
__device__ __half g_wt_p2 [2 * DM * DC];
__device__ __half g_wt_f1 [DFF * DM];
__device__ __half g_wt_f2 [DM * DFF];

// ---------------- helpers ---------------------------------------------------
__device__ __forceinline__ uint32_t smem_u32(const void* p) {
    uint32_t a;
    asm("{ .reg .u64 t; cvta.to.shared.u64 t, %1; cvt.u32.u64 %0, t; }"
        : "=r"(a) : "l"(p));
    return a;
}
__device__ __forceinline__ void cp_async16(uint32_t dst, const void* src) {
    asm volatile("cp.async.cg.shared.global [%0], [%1], 16;"
                 :: "r"(dst), "l"(src) : "memory");
}
#define CP_COMMIT() asm volatile("cp.async.commit_group;" ::: "memory")
#define CP_WAIT(n)  asm volatile("cp.async.wait_group %0;" :: "n"(n) : "memory")

__device__ __forceinline__ void mma_f16(float* c, const uint32_t* a, const uint32_t* b) {
    asm volatile("mma.sync.aligned.m16n8k16.row.col.f32.f16.f16.f32 "
        "{%0,%1,%2,%3}, {%4,%5,%6,%7}, {%8,%9}, {%0,%1,%2,%3};"
        : "+f"(c[0]), "+f"(c[1]), "+f"(c[2]), "+f"(c[3])
        : "r"(a[0]), "r"(a[1]), "r"(a[2]), "r"(a[3]), "r"(b[0]), "r"(b[1]));
}
#define LDMX4(r0, r1, r2, r3, addr)                                           \
    asm volatile("ldmatrix.sync.aligned.m8n8.x4.shared.b16 {%0,%1,%2,%3}, [%4];" \
        : "=r"(r0), "=r"(r1), "=r"(r2), "=r"(r3) : "r"(addr))
#define LDMX4T(r0, r1, r2, r3, addr)                                          \
    asm volatile("ldmatrix.sync.aligned.m8n8.x4.trans.shared.b16 {%0,%1,%2,%3}, [%4];" \
        : "=r"(r0), "=r"(r1), "=r"(r2), "=r"(r3) : "r"(addr))

__device__ __forceinline__ uint32_t packh2(float x, float y) {
    __half2 h = __floats2half2_rn(x, y);
    return *(uint32_t*)&h;
}

// fp16 smem tile: rows of 64 halves = 128B; 16B chunk c (0..7)
#define HXS(r, c) ((uint32_t)((r) * 128 + (((c) ^ ((r) & 7)) << 4)))

// ---------------------------------------------------------------------------
// fp16 mma GEMM (unchanged from round 7)
// ---------------------------------------------------------------------------
#define TG_SMEM 98304

template<int BIAS, int GELU, int RES, int OUTH>
__global__ __launch_bounds__(256) void hgemm(
    const __half* __restrict__ A, const __half* __restrict__ Bt,
    const float* __restrict__ bias, const float* __restrict__ res,
    void* __restrict__ Cv, int M, int N, int K)
{
    extern __shared__ __align__(1024) char smem_raw[];
    const uint32_t sA = smem_u32(smem_raw);
    const uint32_t sB = sA + 3 * 16384;

    const int tid  = threadIdx.x;
    const int wid  = tid >> 5;
    const int lane = tid & 31;
    const int bx = blockIdx.x, by = blockIdx.y;

    const __half* Ab = A  + (size_t)(by * 128) * K;
    const __half* Bb = Bt + (size_t)(bx * 128) * K;
    const int S = K >> 6;

    const int lr = tid >> 3;
    const int lc = tid & 7;

    auto issue = [&](int s, int st) {
        const int k0 = s * 64;
        const uint32_t ao = sA + st * 16384;
        const uint32_t bo = sB + st * 16384;
        #pragma unroll
        for (int t = 0; t < 4; t++) {
            int r = lr + t * 32;
            uint32_t off = HXS(r, lc);
            cp_async16(ao + off, Ab + (size_t)r * K + k0 + lc * 8);
            cp_async16(bo + off, Bb + (size_t)r * K + k0 + lc * 8);
        }
        CP_COMMIT();
    };

    float acc[4][4][4];
    #pragma unroll
    for (int i = 0; i < 4; i++)
        #pragma unroll
        for (int j = 0; j < 4; j++)
            #pragma unroll
            for (int k = 0; k < 4; k++) acc[i][j][k] = 0.f;

    const int wm = (wid >> 2) * 64;
    const int wn = (wid & 3) * 32;
    const int g  = lane >> 2;
    const int tg = lane & 3;
    const int rr  = lane & 7;
    const int sub = lane >> 3;

    uint32_t aRowOff[4], aMask[4];
    const int khalfA = sub >> 1;
    #pragma unroll
    for (int mt = 0; mt < 4; mt++) {
        int row = wm + mt * 16 + (sub & 1) * 8 + rr;
        aRowOff[mt] = (uint32_t)(row * 128);
        aMask[mt]   = (uint32_t)(row & 7);
    }
    uint32_t bRowOff[2], bMask[2];
    const int khalfB = sub & 1;
    #pragma unroll
    for (int ntp = 0; ntp < 2; ntp++) {
        int row = wn + (ntp * 2 + (sub >> 1)) * 8 + rr;
        bRowOff[ntp] = (uint32_t)(row * 128);
        bMask[ntp]   = (uint32_t)(row & 7);
    }

    issue(0, 0);
    issue(1, 1);

    for (int s = 0; s < S; s++) {
        if (s + 1 < S) { CP_WAIT(1); } else { CP_WAIT(0); }
        __syncthreads();
        if (s + 2 < S) issue(s + 2, (s + 2) % 3);

        const uint32_t aBase = sA + (s % 3) * 16384;
        const uint32_t bBase = sB + (s % 3) * 16384;
        #pragma unroll
        for (int kk = 0; kk < 4; kk++) {
            uint32_t a[4][4], b[4][2];
            #pragma unroll
            for (int mt = 0; mt < 4; mt++) {
                uint32_t addr = aBase + aRowOff[mt]
                              + (((uint32_t)(kk * 2 + khalfA) ^ aMask[mt]) << 4);
                LDMX4(a[mt][0], a[mt][1], a[mt][2], a[mt][3], addr);
            }
            #pragma unroll
            for (int ntp = 0; ntp < 2; ntp++) {
                uint32_t addr = bBase + bRowOff[ntp]
                              + (((uint32_t)(kk * 2 + khalfB) ^ bMask[ntp]) << 4);
                LDMX4(b[ntp * 2][0], b[ntp * 2][1], b[ntp * 2 + 1][0], b[ntp * 2 + 1][1], addr);
            }
            #pragma unroll
            for (int mt = 0; mt < 4; mt++)
                #pragma unroll
                for (int nt = 0; nt < 4; nt++)
                    mma_f16(acc[mt][nt], a[mt], b[nt]);
        }
        __syncthreads();
    }

    #pragma unroll
    for (int mt = 0; mt < 4; mt++) {
        #pragma unroll
        for (int hh = 0; hh < 2; hh++) {
            const int row = by * 128 + wm + mt * 16 + g + hh * 8;
            const float* Rr = RES ? (res + (size_t)row * N) : (const float*)0;
            #pragma unroll
            for (int nt = 0; nt < 4; nt++) {
                const int col = bx * 128 + wn + nt * 8 + tg * 2;
                float v0 = acc[mt][nt][hh * 2 + 0];
                float v1 = acc[mt][nt][hh * 2 + 1];
                if (BIAS) { v0 += bias[col]; v1 += bias[col + 1]; }
                if (GELU) {
                    v0 = 0.5f * v0 * (1.f + erff(v0 * 0.70710678118654752f));
                    v1 = 0.5f * v1 * (1.f + erff(v1 * 0.70710678118654752f));
                }
                if (RES) { v0 += Rr[col]; v1 += Rr[col + 1]; }
                if (OUTH) {
                    __half2* Ch = (__half2*)((__half*)Cv + (size_t)row * N + col);
                    *Ch = __floats2half2_rn(v0, v1);
                } else {
                    float2* Cf = (float2*)((float*)Cv + (size_t)row * N + col);
                    *Cf = make_float2(v0, v1);
                }
            }
        }
    }
}

// ---------------------------------------------------------------------------
// fp16 flash attention: m16n8k16, P repacked in registers, V via ldmatrix.trans
// Grid (SEQ/128, NH, B), 256 threads (8 warps x 16 q-rows).
// SMEM: Q[128x64]h 16KB | K 3x[32x64]h 12KB | V 3x 12KB = 40KB
// ---------------------------------------------------------------------------
#define ATT_SMEM 40960
#define NKV      (SEQ / 32)

__global__ __launch_bounds__(256) void fattn(
    const __half* __restrict__ qkv, __half* __restrict__ out)
{
    extern __shared__ __align__(1024) char sm[];
    const uint32_t sb = smem_u32(sm);
    const uint32_t QOFF = 0, KOFF = 16384, VOFF = 28672;

    const int tid = threadIdx.x, wid = tid >> 5, lane = tid & 31;
    const int g = lane >> 2, tg = lane & 3;
    const int rr = lane & 7, sub = lane >> 3;
    const int wm = wid * 16;
    const int qb = blockIdx.x, h = blockIdx.y, b = blockIdx.z;
    const size_t tok0 = (size_t)b * SEQ + (size_t)qb * 128;
    const __half* qbase = qkv + tok0 * (3 * DM) + h * DH;

    // Q: 128 rows x 64 halves = 1024 x 16B chunks (4 per thread)
    #pragma unroll
    for (int t = 0; t < 4; t++) {
        int idx = tid + t * 256;
        int r = idx >> 3, c = idx & 7;
        cp_async16(sb + QOFF + HXS(r, c), qbase + (size_t)r * (3 * DM) + c * 8);
    }
    // KV tile: 32x64 halves = 256 chunks per operand; K threads 0-127 (2 each), V 128-255
    auto issue_kv = [&](int it) {
        const int buf = it % 3;
        const uint32_t base = sb + (tid < 128 ? KOFF : VOFF) + buf * 4096;
        const int seg = (tid < 128 ? DM : 2 * DM);
        #pragma unroll
        for (int t = 0; t < 2; t++) {
            const int chunk = (tid & 127) + t * 128;
            const int r = chunk >> 3, c = chunk & 7;
            cp_async16(base + HXS(r, c),
                       qkv + ((size_t)b * SEQ + it * 32 + r) * (3 * DM) + seg + h * DH + c * 8);
        }
        CP_COMMIT();
    };
    issue_kv(0);   // group 0 = Q + kv0
    issue_kv(1);
    issue_kv(2);

    CP_WAIT(2);
    __syncthreads();

    // Q fragments (4 k16-steps over DH=64)
    uint32_t qf[4][4];
    {
        const int row = wm + (sub & 1) * 8 + rr;
        const uint32_t rowOff = (uint32_t)(row * 128);
        const uint32_t mask = (uint32_t)(row & 7);
        const int khalf = sub >> 1;
        #pragma unroll
        for (int kk = 0; kk < 4; kk++) {
            uint32_t addr = sb + QOFF + rowOff + (((uint32_t)(kk * 2 + khalf) ^ mask) << 4);
            LDMX4(qf[kk][0], qf[kk][1], qf[kk][2], qf[kk][3], addr);
        }
    }

    float oa[8][4];
    #pragma unroll
    for (int i = 0; i < 8; i++)
        #pragma unroll
        for (int j = 0; j < 4; j++) oa[i][j] = 0.f;
    float m0 = -1e30f, m1 = -1e30f, l0 = 0.f, l1 = 0.f;

    // K-side ldmatrix address components
    const int kRow = (sub >> 1) * 8 + rr;       // within a 16-row pair group
    const int kHalf = sub & 1;

    for (int it = 0; it < NKV; it++) {
        if (it < NKV - 2)      { CP_WAIT(2); }
        else if (it == NKV - 2){ CP_WAIT(1); }
        else                   { CP_WAIT(0); }
        __syncthreads();

        const int buf = it % 3;
        const uint32_t kbuf = sb + KOFF + buf * 4096;
        const uint32_t vbuf = sb + VOFF + buf * 4096;

        // ---- S = Q @ K^T (fp16 mma, fp32 accum) ----
        float sf[4][4];
        #pragma unroll
        for (int nt = 0; nt < 4; nt++)
            #pragma unroll
            for (int e = 0; e < 4; e++) sf[nt][e] = 0.f;

        #pragma unroll
        for (int kk = 0; kk < 4; kk++) {
            uint32_t bfr[4][2];
            #pragma unroll
            for (int ntp = 0; ntp < 2; ntp++) {
                const int row = ntp * 16 + kRow;
                uint32_t addr = kbuf + (uint32_t)(row * 128)
                              + (((uint32_t)(kk * 2 + kHalf) ^ (uint32_t)(row & 7)) << 4);
                LDMX4(bfr[ntp * 2][0], bfr[ntp * 2][1],
                      bfr[ntp * 2 + 1][0], bfr[ntp * 2 + 1][1], addr);
            }
            #pragma unroll
            for (int nt = 0; nt < 4; nt++)
                mma_f16(sf[nt], qf[kk], bfr[nt]);
        }

        // ---- online softmax ----
        float mx0 = -1e30f, mx1 = -1e30f;
        #pragma unroll
        for (int nt = 0; nt < 4; nt++) {
            #pragma unroll
            for (int e = 0; e < 4; e++) sf[nt][e] *= 0.125f;
            mx0 = fmaxf(mx0, fmaxf(sf[nt][0], sf[nt][1]));
            mx1 = fmaxf(mx1, fmaxf(sf[nt][2], sf[nt][3]));
        }
        mx0 = fmaxf(mx0, __shfl_xor_sync(0xffffffffu, mx0, 1));
        mx0 = fmaxf(mx0, __shfl_xor_sync(0xffffffffu, mx0, 2));
        mx1 = fmaxf(mx1, __shfl_xor_sync(0xffffffffu, mx1, 1));
        mx1 = fmaxf(mx1, __shfl_xor_sync(0xffffffffu, mx1, 2));
        const float nm0 = fmaxf(m0, mx0), nm1 = fmaxf(m1, mx1);
        const float cr0 = __expf(m0 - nm0), cr1 = __expf(m1 - nm1);
        m0 = nm0; m1 = nm1;

        float ls0 = 0.f, ls1 = 0.f;
        #pragma unroll
        for (int nt = 0; nt < 4; nt++) {
            sf[nt][0] = __expf(sf[nt][0] - m0);
            sf[nt][1] = __expf(sf[nt][1] - m0);
            sf[nt][2] = __expf(sf[nt][2] - m1);
            sf[nt][3] = __expf(sf[nt][3] - m1);
            ls0 += sf[nt][0] + sf[nt][1];
            ls1 += sf[nt][2] + sf[nt][3];
        }
        ls0 += __shfl_xor_sync(0xffffffffu, ls0, 1);
        ls0 += __shfl_xor_sync(0xffffffffu, ls0, 2);
        ls1 += __shfl_xor_sync(0xffffffffu, ls1, 1);
        ls1 += __shfl_xor_sync(0xffffffffu, ls1, 2);
        l0 = l0 * cr0 + ls0;
        l1 = l1 * cr1 + ls1;

        #pragma unroll
        for (int nt = 0; nt < 8; nt++) {
            oa[nt][0] *= cr0; oa[nt][1] *= cr0;
            oa[nt][2] *= cr1; oa[nt][3] *= cr1;
        }

        // ---- O += P @ V (P repacked in registers; V via ldmatrix.trans) ----
        #pragma unroll
        for (int kk = 0; kk < 2; kk++) {   // keys kk*16..+15
            uint32_t a[4];
            a[0] = packh2(sf[kk * 2][0],     sf[kk * 2][1]);
            a[1] = packh2(sf[kk * 2][2],     sf[kk * 2][3]);
            a[2] = packh2(sf[kk * 2 + 1][0], sf[kk * 2 + 1][1]);
            a[3] = packh2(sf[kk * 2 + 1][2], sf[kk * 2 + 1][3]);
            const int key = kk * 16 + (sub & 1) * 8 + rr;
            const uint32_t keyOff = (uint32_t)(key * 128);
            const uint32_t keyMask = (uint32_t)(key & 7);
            #pragma unroll
            for (int ntp = 0; ntp < 4; ntp++) {   // dims ntp*16..+15
                uint32_t b0[2], b1[2];
                uint32_t addr = vbuf + keyOff
                              + (((uint32_t)(ntp * 2 + (sub >> 1)) ^ keyMask) << 4);
                LDMX4T(b0[0], b0[1], b1[0], b1[1], addr);
                mma_f16(oa[ntp * 2],     a, b0);
                mma_f16(oa[ntp * 2 + 1], a, b1);
            }
        }
        __syncthreads();
        if (it + 3 < NKV) issue_kv(it + 3);
    }

    // ---- epilogue ----
    const float inv0 = 1.f / l0, inv1 = 1.f / l1;
    #pragma unroll
    for (int nt = 0; nt < 8; nt++) {
        const int col = h * DH + nt * 8 + 2 * tg;
        __half* o0 = out + (tok0 + wm + g) * DM + col;
        __half* o1 = out + (tok0 + wm + g + 8) * DM + col;
        *(__half2*)o0 = __floats2half2_rn(oa[nt][0] * inv0, oa[nt][1] * inv0);
        *(__half2*)o1 = __floats2half2_rn(oa[nt][2] * inv1, oa[nt][3] * inv1);
    }
}

// ---------------------------------------------------------------------------
// Weight transpose to fp16
// ---------------------------------------------------------------------------
__global__ __launch_bounds__(256) void transpose_h(
    const float* __restrict__ W, __half* __restrict__ Wt, int K, int N)
{
    __shared__ float t[32][33];
    int n0 = blockIdx.x * 32, k0 = blockIdx.y * 32;
    int tx = threadIdx.x & 31, ty = threadIdx.x >> 5;
    #pragma unroll
    for (int i = 0; i < 32; i += 8)
        t[ty + i][tx] = W[(size_t)(k0 + ty + i) * N + n0 + tx];
    __syncthreads();
    #pragma unroll
    for (int i = 0; i < 32; i += 8)
        Wt[(size_t)(n0 + ty + i) * K + k0 + tx] = __float2half_rn(t[tx][ty + i]);
}

// ---------------------------------------------------------------------------
// silu -> fp16
// ---------------------------------------------------------------------------
__global__ void silu_kernel(const float* __restrict__ in, __half* __restrict__ out, int n4) {
    int i = blockIdx.x * blockDim.x + threadIdx.x;
    if (i >= n4) return;
    float4 v = ((const float4*)in)[i];
    __half2 a = __floats2half2_rn(v.x / (1.f + expf(-v.x)), v.y / (1.f + expf(-v.y)));
    __half2 b = __floats2half2_rn(v.z / (1.f + expf(-v.z)), v.w / (1.f + expf(-v.w)));
    __half2* o = (__half2*)(out + (size_t)i * 4);
    o[0] = a; o[1] = b;
}

// ---------------------------------------------------------------------------
// AdaLN -> fp16
// ---------------------------------------------------------------------------
__global__ __launch_bounds__(256) void adaln_kernel(
    const float* __restrict__ x, const float* __restrict__ gb, __half* __restrict__ out)
{
    int row = blockIdx.x;
    const float* xr = x + (size_t)row * DM;
    int i = threadIdx.x * 4;
    float4 v = *(const float4*)(xr + i);
    float s  = v.x + v.y + v.z + v.w;
    float ss = v.x*v.x + v.y*v.y + v.z*v.z + v.w*v.w;
    #pragma unroll
    for (int o = 16; o > 0; o >>= 1) {
        s  += __shfl_xor_sync(0xffffffffu, s,  o);
        ss += __shfl_xor_sync(0xffffffffu, ss, o);
    }
    __shared__ float sh[16];
    int w = threadIdx.x >> 5, ln = threadIdx.x & 31;
    if (ln == 0) { sh[w] = s; sh[w + 8] = ss; }
    __syncthreads();
    float fs = 0.f, fss = 0.f;
    #pragma unroll
    for (int k = 0; k < 8; k++) { fs += sh[k]; fss += sh[k + 8]; }
    float mu   = fs  * (1.f / DM);
    float var  = fss * (1.f / DM) - mu * mu;
    float rstd = rsqrtf(var + 1e-5f);

    const float* gp = gb + (size_t)row * (2 * DM);
    float4 ga = *(const float4*)(gp + i);
    float4 be = *(const float4*)(gp + DM + i);
    float o0 = (v.x - mu) * rstd * (1.f + ga.x) + be.x;
    float o1 = (v.y - mu) * rstd * (1.f + ga.y) + be.y;
    float o2 = (v.z - mu) * rstd * (1.f + ga.z) + be.z;
    float o3 = (v.w - mu) * rstd * (1.f + ga.w) + be.w;
    __half2* op = (__half2*)(out + (size_t)row * DM + i);
    op[0] = __floats2half2_rn(o0, o1);
    op[1] = __floats2half2_rn(o2, o3);
}

// ---------------------------------------------------------------------------
// Launch
// ---------------------------------------------------------------------------
extern "C" void kernel_launch(void* const* d_in, const int* in_sizes, int n_in,
                              void* d_out, int out_size)
{
    const float* x          = (const float*)d_in[0];
    const float* cond       = (const float*)d_in[1];
    const float* p1_w       = (const float*)d_in[2];
    const float* p1_b       = (const float*)d_in[3];
    const float* qkv_w      = (const float*)d_in[4];
    const float* attn_out_w = (const float*)d_in[5];
    const float* p2_w       = (const float*)d_in[6];
    const float* p2_b       = (const float*)d_in[7];
    const float* ffn_w1     = (const float*)d_in[8];
    const float* ffn_b1     = (const float*)d_in[9];
    const float* ffn_w2     = (const float*)d_in[10];
    const float* ffn_b2     = (const float*)d_in[11];
    float* out = (float*)d_out;

    __half *sc, *h, *attn, *ff, *qkv;
    float *gb, *x2;
    __half *wt_p1, *wt_qkv, *wt_ao, *wt_p2, *wt_f1, *wt_f2;
    cudaGetSymbolAddress((void**)&sc,    g_sc);
    cudaGetSymbolAddress((void**)&gb,    g_gb);
    cudaGetSymbolAddress((void**)&h,     g_h);
    cudaGetSymbolAddress((void**)&qkv,   g_qkv);
    cudaGetSymbolAddress((void**)&attn,  g_attn);
    cudaGetSymbolAddress((void**)&x2,    g_x2);
    cudaGetSymbolAddress((void**)&ff,    g_ff);
    cudaGetSymbolAddress((void**)&wt_p1,  g_wt_p1);
    cudaGetSymbolAddress((void**)&wt_qkv, g_wt_qkv);
    cudaGetSymbolAddress((void**)&wt_ao,  g_wt_ao);
    cudaGetSymbolAddress((void**)&wt_p2,  g_wt_p2);
    cudaGetSymbolAddress((void**)&wt_f1,  g_wt_f1);
    cudaGetSymbolAddress((void**)&wt_f2,  g_wt_f2);

    cudaFuncSetAttribute(hgemm<1,0,0,0>, cudaFuncAttributeMaxDynamicSharedMemorySize, TG_SMEM);
    cudaFuncSetAttribute(hgemm<0,0,0,1>, cudaFuncAttributeMaxDynamicSharedMemorySize, TG_SMEM);
    cudaFuncSetAttribute(hgemm<0,0,1,0>, cudaFuncAttributeMaxDynamicSharedMemorySize, TG_SMEM);
    cudaFuncSetAttribute(hgemm<1,1,0,1>, cudaFuncAttributeMaxDynamicSharedMemorySize, TG_SMEM);
    cudaFuncSetAttribute(hgemm<1,0,1,0>, cudaFuncAttributeMaxDynamicSharedMemorySize, TG_SMEM);
    cudaFuncSetAttribute(fattn, cudaFuncAttributeMaxDynamicSharedMemorySize, ATT_SMEM);

    transpose_h<<<dim3(2048/32,  512/32), 256>>>(p1_w,       wt_p1,  512,  2048);
    transpose_h<<<dim3(3072/32, 1024/32), 256>>>(qkv_w,      wt_qkv, 1024, 3072);
    transpose_h<<<dim3(1024/32, 1024/32), 256>>>(attn_out_w, wt_ao,  1024, 1024);
    transpose_h<<<dim3(2048/32,  512/32), 256>>>(p2_w,       wt_p2,  512,  2048);
    transpose_h<<<dim3(4096/32, 1024/32), 256>>>(ffn_w1,     wt_f1,  1024, 4096);
    transpose_h<<<dim3(1024/32, 4096/32), 256>>>(ffn_w2,     wt_f2,  4096, 1024);

    // 1. sc = silu(cond) -> fp16
    silu_kernel<<<(BS_TOK * DC / 4 + 255) / 256, 256>>>(cond, sc, BS_TOK * DC / 4);
    // 2. gb = sc @ p1_w + p1_b (fp32 out)
    hgemm<1,0,0,0><<<dim3(2048/128, BS_TOK/128), 256, TG_SMEM>>>(
        sc, wt_p1, p1_b, nullptr, gb, BS_TOK, 2048, DC);
    // 3. h = adaln(x, gb) -> fp16
    adaln_kernel<<<BS_TOK, 256>>>(x, gb, h);
    // 4. qkv = h @ qkv_w -> fp16
    hgemm<0,0,0,1><<<dim3(3072/128, BS_TOK/128), 256, TG_SMEM>>>(
        h, wt_qkv, nullptr, nullptr, qkv, BS_TOK, 3072, DM);
    // 5. attention (fp16) -> fp16
    fattn<<<dim3(SEQ/128, NH, 2), 256, ATT_SMEM>>>(qkv, attn);
    // 6. x2 = x + attn @ attn_out_w (fp32 out)
    hgemm<0,0,1,0><<<dim3(1024/128, BS_TOK/128), 256, TG_SMEM>>>(
        attn, wt_ao, nullptr, x, x2, BS_TOK, 1024, DM);
    // 7. gb = sc @ p2_w + p2_b
    hgemm<1,0,0,0><<<dim3(2048/128, BS_TOK/128), 256, TG_SMEM>>>(
        sc, wt_p2, p2_b, nullptr, gb, BS_TOK, 2048, DC);
    // 8. h = adaln(x2, gb) -> fp16
    adaln_kernel<<<BS_TOK, 256>>>(x2, gb, h);
    // 9. ff = gelu(h @ ffn_w1 + ffn_b1) -> fp16
    hgemm<1,1,0,1><<<dim3(DFF/128, BS_TOK/128), 256, TG_SMEM>>>(
        h, wt_f1, ffn_b1, nullptr, ff, BS_TOK, DFF, DM);
    // 10. out = x2 + ff @ ffn_w2 + ffn_b2 (fp32 out)
    hgemm<1,0,1,0><<<dim3(1024/128, BS_TOK/128), 256, TG_SMEM>>>(
        ff, wt_f2, ffn_b2, x2, out, BS_TOK, 1024, DFF);
}

// round 11
// speedup vs baseline: 7.5533x; 1.0102x over previous
#include <cuda_runtime.h>
#include <cuda_fp16.h>
#include <math.h>
#include <stdint.h>

// ---------------------------------------------------------------------------
// DecoderBlock: B=2, S=2048, D_MODEL=1024, D_COND=512, H=16, d=64, FF=4096
// Round 11: hgemm at 2 CTAs/SM (__launch_bounds__(256,2)); p1+p2 merged into
// a single N=4096 GEMM over concatenated weights. Attention as round 8.
// ---------------------------------------------------------------------------

#define BS_TOK   4096
#define DM       1024
#define DC       512
#define DFF      4096
#define NH       16
#define DH       64
#define SEQ      2048

// ---------------- scratch ---------------------------------------------------
__device__ __half g_sc  [BS_TOK * DC];
__device__ float  g_gb  [BS_TOK * 4 * DM];   // merged: [tok, 4096] (p1 gb | p2 gb)
__device__ __half g_h   [BS_TOK * DM];
__device__ __half g_qkv [BS_TOK * 3 * DM];
__device__ __half g_attn[BS_TOK * DM];
__device__ float  g_x2  [BS_TOK * DM];
__device__ __half g_ff  [BS_TOK * DFF];
__device__ __half g_wt_p12[4 * DM * DC];     // rows 0..2047: p1^T, 2048..4095: p2^T
__device__ __half g_wt_qkv[3 * DM * DM];
__device__ __half g_wt_ao [DM * DM];
__device__ __half g_wt_f1 [DFF * DM];
__device__ __half g_wt_f2 [DM * DFF];
__device__ float  g_b_p12 [4 * DM];          // concatenated p1_b | p2_b

// ---------------- helpers ---------------------------------------------------
__device__ __forceinline__ uint32_t smem_u32(const void* p) {
    uint32_t a;
    asm("{ .reg .u64 t; cvta.to.shared.u64 t, %1; cvt.u32.u64 %0, t; }"
        : "=r"(a) : "l"(p));
    return a;
}
__device__ __forceinline__ void cp_async16(uint32_t dst, const void* src) {
    asm volatile("cp.async.cg.shared.global [%0], [%1], 16;"
                 :: "r"(dst), "l"(src) : "memory");
}
#define CP_COMMIT() asm volatile("cp.async.commit_group;" ::: "memory")
#define CP_WAIT(n)  asm volatile("cp.async.wait_group %0;" :: "n"(n) : "memory")

__device__ __forceinline__ void mma_f16(float* c, const uint32_t* a, const uint32_t* b) {
    asm volatile("mma.sync.aligned.m16n8k16.row.col.f32.f16.f16.f32 "
        "{%0,%1,%2,%3}, {%4,%5,%6,%7}, {%8,%9}, {%0,%1,%2,%3};"
        : "+f"(c[0]), "+f"(c[1]), "+f"(c[2]), "+f"(c[3])
        : "r"(a[0]), "r"(a[1]), "r"(a[2]), "r"(a[3]), "r"(b[0]), "r"(b[1]));
}
#define LDMX4(r0, r1, r2, r3, addr)                                           \
    asm volatile("ldmatrix.sync.aligned.m8n8.x4.shared.b16 {%0,%1,%2,%3}, [%4];" \
        : "=r"(r0), "=r"(r1), "=r"(r2), "=r"(r3) : "r"(addr))
#define LDMX4T(r0, r1, r2, r3, addr)                                          \
    asm volatile("ldmatrix.sync.aligned.m8n8.x4.trans.shared.b16 {%0,%1,%2,%3}, [%4];" \
        : "=r"(r0), "=r"(r1), "=r"(r2), "=r"(r3) : "r"(addr))

__device__ __forceinline__ uint32_t packh2(float x, float y) {
    __half2 h = __floats2half2_rn(x, y);
    return *(uint32_t*)&h;
}

#define HXS(r, c) ((uint32_t)((r) * 128 + (((c) ^ ((r) & 7)) << 4)))

// ---------------------------------------------------------------------------
// fp16 mma GEMM: C[M,N] = A[M,K] @ Bt[N,K]^T (+bias)(+gelu)(+res)
// BM=BN=128, BK=64, 3-stage cp.async, 256 threads, 2 CTAs/SM.
// ---------------------------------------------------------------------------
#define TG_SMEM 98304

template<int BIAS, int GELU, int RES, int OUTH>
__global__ __launch_bounds__(256, 2) void hgemm(
    const __half* __restrict__ A, const __half* __restrict__ Bt,
    const float* __restrict__ bias, const float* __restrict__ res,
    void* __restrict__ Cv, int M, int N, int K)
{
    extern __shared__ __align__(1024) char smem_raw[];
    const uint32_t sA = smem_u32(smem_raw);
    const uint32_t sB = sA + 3 * 16384;

    const int tid  = threadIdx.x;
    const int wid  = tid >> 5;
    const int lane = tid & 31;
    const int bx = blockIdx.x, by = blockIdx.y;

    const __half* Ab = A  + (size_t)(by * 128) * K;
    const __half* Bb = Bt + (size_t)(bx * 128) * K;
    const int S = K >> 6;

    const int lr = tid >> 3;
    const int lc = tid & 7;

    auto issue = [&](int s, int st) {
        const int k0 = s * 64;
        const uint32_t ao = sA + st * 16384;
        const uint32_t bo = sB + st * 16384;
        #pragma unroll
        for (int t = 0; t < 4; t++) {
            int r = lr + t * 32;
            uint32_t off = HXS(r, lc);
            cp_async16(ao + off, Ab + (size_t)r * K + k0 + lc * 8);
            cp_async16(bo + off, Bb + (size_t)r * K + k0 + lc * 8);
        }
        CP_COMMIT();
    };

    float acc[4][4][4];
    #pragma unroll
    for (int i = 0; i < 4; i++)
        #pragma unroll
        for (int j = 0; j < 4; j++)
            #pragma unroll
            for (int k = 0; k < 4; k++) acc[i][j][k] = 0.f;

    const int wm = (wid >> 2) * 64;
    const int wn = (wid & 3) * 32;
    const int g  = lane >> 2;
    const int tg = lane & 3;
    const int rr  = lane & 7;
    const int sub = lane >> 3;

    uint32_t aRowOff[4], aMask[4];
    const int khalfA = sub >> 1;
    #pragma unroll
    for (int mt = 0; mt < 4; mt++) {
        int row = wm + mt * 16 + (sub & 1) * 8 + rr;
        aRowOff[mt] = (uint32_t)(row * 128);
        aMask[mt]   = (uint32_t)(row & 7);
    }
    uint32_t bRowOff[2], bMask[2];
    const int khalfB = sub & 1;
    #pragma unroll
    for (int ntp = 0; ntp < 2; ntp++) {
        int row = wn + (ntp * 2 + (sub >> 1)) * 8 + rr;
        bRowOff[ntp] = (uint32_t)(row * 128);
        bMask[ntp]   = (uint32_t)(row & 7);
    }

    issue(0, 0);
    issue(1, 1);

    for (int s = 0; s < S; s++) {
        if (s + 1 < S) { CP_WAIT(1); } else { CP_WAIT(0); }
        __syncthreads();
        if (s + 2 < S) issue(s + 2, (s + 2) % 3);

        const uint32_t aBase = sA + (s % 3) * 16384;
        const uint32_t bBase = sB + (s % 3) * 16384;
        #pragma unroll
        for (int kk = 0; kk < 4; kk++) {
            uint32_t a[4][4], b[4][2];
            #pragma unroll
            for (int mt = 0; mt < 4; mt++) {
                uint32_t addr = aBase + aRowOff[mt]
                              + (((uint32_t)(kk * 2 + khalfA) ^ aMask[mt]) << 4);
                LDMX4(a[mt][0], a[mt][1], a[mt][2], a[mt][3], addr);
            }
            #pragma unroll
            for (int ntp = 0; ntp < 2; ntp++) {
                uint32_t addr = bBase + bRowOff[ntp]
                              + (((uint32_t)(kk * 2 + khalfB) ^ bMask[ntp]) << 4);
                LDMX4(b[ntp * 2][0], b[ntp * 2][1], b[ntp * 2 + 1][0], b[ntp * 2 + 1][1], addr);
            }
            #pragma unroll
            for (int mt = 0; mt < 4; mt++)
                #pragma unroll
                for (int nt = 0; nt < 4; nt++)
                    mma_f16(acc[mt][nt], a[mt], b[nt]);
        }
        __syncthreads();
    }

    #pragma unroll
    for (int mt = 0; mt < 4; mt++) {
        #pragma unroll
        for (int hh = 0; hh < 2; hh++) {
            const int row = by * 128 + wm + mt * 16 + g + hh * 8;
            const float* Rr = RES ? (res + (size_t)row * N) : (const float*)0;
            #pragma unroll
            for (int nt = 0; nt < 4; nt++) {
                const int col = bx * 128 + wn + nt * 8 + tg * 2;
                float v0 = acc[mt][nt][hh * 2 + 0];
                float v1 = acc[mt][nt][hh * 2 + 1];
                if (BIAS) { v0 += bias[col]; v1 += bias[col + 1]; }
                if (GELU) {
                    v0 = 0.5f * v0 * (1.f + erff(v0 * 0.70710678118654752f));
                    v1 = 0.5f * v1 * (1.f + erff(v1 * 0.70710678118654752f));
                }
                if (RES) { v0 += Rr[col]; v1 += Rr[col + 1]; }
                if (OUTH) {
                    __half2* Ch = (__half2*)((__half*)Cv + (size_t)row * N + col);
                    *Ch = __floats2half2_rn(v0, v1);
                } else {
                    float2* Cf = (float2*)((float*)Cv + (size_t)row * N + col);
                    *Cf = make_float2(v0, v1);
                }
            }
        }
    }
}

// ---------------------------------------------------------------------------
// fp16 flash attention (unchanged from round 8)
// ---------------------------------------------------------------------------
#define ATT_SMEM 40960
#define NKV      (SEQ / 32)

__global__ __launch_bounds__(256) void fattn(
    const __half* __restrict__ qkv, __half* __restrict__ out)
{
    extern __shared__ __align__(1024) char sm[];
    const uint32_t sb = smem_u32(sm);
    const uint32_t QOFF = 0, KOFF = 16384, VOFF = 28672;

    const int tid = threadIdx.x, wid = tid >> 5, lane = tid & 31;
    const int g = lane >> 2, tg = lane & 3;
    const int rr = lane & 7, sub = lane >> 3;
    const int wm = wid * 16;
    const int qb = blockIdx.x, h = blockIdx.y, b = blockIdx.z;
    const size_t tok0 = (size_t)b * SEQ + (size_t)qb * 128;
    const __half* qbase = qkv + tok0 * (3 * DM) + h * DH;

    #pragma unroll
    for (int t = 0; t < 4; t++) {
        int idx = tid + t * 256;
        int r = idx >> 3, c = idx & 7;
        cp_async16(sb + QOFF + HXS(r, c), qbase + (size_t)r * (3 * DM) + c * 8);
    }
    auto issue_kv = [&](int it) {
        const int buf = it % 3;
        const uint32_t base = sb + (tid < 128 ? KOFF : VOFF) + buf * 4096;
        const int seg = (tid < 128 ? DM : 2 * DM);
        #pragma unroll
        for (int t = 0; t < 2; t++) {
            const int chunk = (tid & 127) + t * 128;
            const int r = chunk >> 3, c = chunk & 7;
            cp_async16(base + HXS(r, c),
                       qkv + ((size_t)b * SEQ + it * 32 + r) * (3 * DM) + seg + h * DH + c * 8);
        }
        CP_COMMIT();
    };
    issue_kv(0);
    issue_kv(1);
    issue_kv(2);

    CP_WAIT(2);
    __syncthreads();

    uint32_t qf[4][4];
    {
        const int row = wm + (sub & 1) * 8 + rr;
        const uint32_t rowOff = (uint32_t)(row * 128);
        const uint32_t mask = (uint32_t)(row & 7);
        const int khalf = sub >> 1;
        #pragma unroll
        for (int kk = 0; kk < 4; kk++) {
            uint32_t addr = sb + QOFF + rowOff + (((uint32_t)(kk * 2 + khalf) ^ mask) << 4);
            LDMX4(qf[kk][0], qf[kk][1], qf[kk][2], qf[kk][3], addr);
        }
    }

    float oa[8][4];
    #pragma unroll
    for (int i = 0; i < 8; i++)
        #pragma unroll
        for (int j = 0; j < 4; j++) oa[i][j] = 0.f;
    float m0 = -1e30f, m1 = -1e30f, l0 = 0.f, l1 = 0.f;

    const int kRow = (sub >> 1) * 8 + rr;
    const int kHalf = sub & 1;

    for (int it = 0; it < NKV; it++) {
        if (it < NKV - 2)      { CP_WAIT(2); }
        else if (it == NKV - 2){ CP_WAIT(1); }
        else                   { CP_WAIT(0); }
        __syncthreads();

        const int buf = it % 3;
        const uint32_t kbuf = sb + KOFF + buf * 4096;
        const uint32_t vbuf = sb + VOFF + buf * 4096;

        float sf[4][4];
        #pragma unroll
        for (int nt = 0; nt < 4; nt++)
            #pragma unroll
            for (int e = 0; e < 4; e++) sf[nt][e] = 0.f;

        #pragma unroll
        for (int kk = 0; kk < 4; kk++) {
            uint32_t bfr[4][2];
            #pragma unroll
            for (int ntp = 0; ntp < 2; ntp++) {
                const int row = ntp * 16 + kRow;
                uint32_t addr = kbuf + (uint32_t)(row * 128)
                              + (((uint32_t)(kk * 2 + kHalf) ^ (uint32_t)(row & 7)) << 4);
                LDMX4(bfr[ntp * 2][0], bfr[ntp * 2][1],
                      bfr[ntp * 2 + 1][0], bfr[ntp * 2 + 1][1], addr);
            }
            #pragma unroll
            for (int nt = 0; nt < 4; nt++)
                mma_f16(sf[nt], qf[kk], bfr[nt]);
        }

        float mx0 = -1e30f, mx1 = -1e30f;
        #pragma unroll
        for (int nt = 0; nt < 4; nt++) {
            #pragma unroll
            for (int e = 0; e < 4; e++) sf[nt][e] *= 0.125f;
            mx0 = fmaxf(mx0, fmaxf(sf[nt][0], sf[nt][1]));
            mx1 = fmaxf(mx1, fmaxf(sf[nt][2], sf[nt][3]));
        }
        mx0 = fmaxf(mx0, __shfl_xor_sync(0xffffffffu, mx0, 1));
        mx0 = fmaxf(mx0, __shfl_xor_sync(0xffffffffu, mx0, 2));
        mx1 = fmaxf(mx1, __shfl_xor_sync(0xffffffffu, mx1, 1));
        mx1 = fmaxf(mx1, __shfl_xor_sync(0xffffffffu, mx1, 2));
        const float nm0 = fmaxf(m0, mx0), nm1 = fmaxf(m1, mx1);
        const float cr0 = __expf(m0 - nm0), cr1 = __expf(m1 - nm1);
        m0 = nm0; m1 = nm1;

        float ls0 = 0.f, ls1 = 0.f;
        #pragma unroll
        for (int nt = 0; nt < 4; nt++) {
            sf[nt][0] = __expf(sf[nt][0] - m0);
            sf[nt][1] = __expf(sf[nt][1] - m0);
            sf[nt][2] = __expf(sf[nt][2] - m1);
            sf[nt][3] = __expf(sf[nt][3] - m1);
            ls0 += sf[nt][0] + sf[nt][1];
            ls1 += sf[nt][2] + sf[nt][3];
        }
        ls0 += __shfl_xor_sync(0xffffffffu, ls0, 1);
        ls0 += __shfl_xor_sync(0xffffffffu, ls0, 2);
        ls1 += __shfl_xor_sync(0xffffffffu, ls1, 1);
        ls1 += __shfl_xor_sync(0xffffffffu, ls1, 2);
        l0 = l0 * cr0 + ls0;
        l1 = l1 * cr1 + ls1;

        #pragma unroll
        for (int nt = 0; nt < 8; nt++) {
            oa[nt][0] *= cr0; oa[nt][1] *= cr0;
            oa[nt][2] *= cr1; oa[nt][3] *= cr1;
        }

        #pragma unroll
        for (int kk = 0; kk < 2; kk++) {
            uint32_t a[4];
            a[0] = packh2(sf[kk * 2][0],     sf[kk * 2][1]);
            a[1] = packh2(sf[kk * 2][2],     sf[kk * 2][3]);
            a[2] = packh2(sf[kk * 2 + 1][0], sf[kk * 2 + 1][1]);
            a[3] = packh2(sf[kk * 2 + 1][2], sf[kk * 2 + 1][3]);
            const int key = kk * 16 + (sub & 1) * 8 + rr;
            const uint32_t keyOff = (uint32_t)(key * 128);
            const uint32_t keyMask = (uint32_t)(key & 7);
            #pragma unroll
            for (int ntp = 0; ntp < 4; ntp++) {
                uint32_t b0[2], b1[2];
                uint32_t addr = vbuf + keyOff
                              + (((uint32_t)(ntp * 2 + (sub >> 1)) ^ keyMask) << 4);
                LDMX4T(b0[0], b0[1], b1[0], b1[1], addr);
                mma_f16(oa[ntp * 2],     a, b0);
                mma_f16(oa[ntp * 2 + 1], a, b1);
            }
        }
        __syncthreads();
        if (it + 3 < NKV) issue_kv(it + 3);
    }

    const float inv0 = 1.f / l0, inv1 = 1.f / l1;
    #pragma unroll
    for (int nt = 0; nt < 8; nt++) {
        const int col = h * DH + nt * 8 + 2 * tg;
        __half* o0 = out + (tok0 + wm + g) * DM + col;
        __half* o1 = out + (tok0 + wm + g + 8) * DM + col;
        *(__half2*)o0 = __floats2half2_rn(oa[nt][0] * inv0, oa[nt][1] * inv0);
        *(__half2*)o1 = __floats2half2_rn(oa[nt][2] * inv1, oa[nt][3] * inv1);
    }
}

// ---------------------------------------------------------------------------
// Weight transpose to fp16
// ---------------------------------------------------------------------------
__global__ __launch_bounds__(256) void transpose_h(
    const float* __restrict__ W, __half* __restrict__ Wt, int K, int N)
{
    __shared__ float t[32][33];
    int n0 = blockIdx.x * 32, k0 = blockIdx.y * 32;
    int tx = threadIdx.x & 31, ty = threadIdx.x >> 5;
    #pragma unroll
    for (int i = 0; i < 32; i += 8)
        t[ty + i][tx] = W[(size_t)(k0 + ty + i) * N + n0 + tx];
    __syncthreads();
    #pragma unroll
    for (int i = 0; i < 32; i += 8)
        Wt[(size_t)(n0 + ty + i) * K + k0 + tx] = __float2half_rn(t[tx][ty + i]);
}

// concat biases: out[0:2048) = b1, [2048:4096) = b2
__global__ void concat_bias(const float* __restrict__ b1, const float* __restrict__ b2,
                            float* __restrict__ o) {
    int i = blockIdx.x * blockDim.x + threadIdx.x;
    if (i < 2 * DM) o[i] = b1[i];
    else            o[i] = b2[i - 2 * DM];
}

// ---------------------------------------------------------------------------
// silu -> fp16
// ---------------------------------------------------------------------------
__global__ void silu_kernel(const float* __restrict__ in, __half* __restrict__ out, int n4) {
    int i = blockIdx.x * blockDim.x + threadIdx.x;
    if (i >= n4) return;
    float4 v = ((const float4*)in)[i];
    __half2 a = __floats2half2_rn(v.x / (1.f + expf(-v.x)), v.y / (1.f + expf(-v.y)));
    __half2 b = __floats2half2_rn(v.z / (1.f + expf(-v.z)), v.w / (1.f + expf(-v.w)));
    __half2* o = (__half2*)(out + (size_t)i * 4);
    o[0] = a; o[1] = b;
}

// ---------------------------------------------------------------------------
// AdaLN -> fp16 (reads merged gb buffer: gamma at gbo[i], beta at gbo[DM+i])
// ---------------------------------------------------------------------------
__global__ __launch_bounds__(256) void adaln_kernel(
    const float* __restrict__ x, const float* __restrict__ gb, int gbStride,
    int gbOff, __half* __restrict__ out)
{
    int row = blockIdx.x;
    const float* xr = x + (size_t)row * DM;
    int i = threadIdx.x * 4;
    float4 v = *(const float4*)(xr + i);
    float s  = v.x + v.y + v.z + v.w;
    float ss = v.x*v.x + v.y*v.y + v.z*v.z + v.w*v.w;
    #pragma unroll
    for (int o = 16; o > 0; o >>= 1) {
        s  += __shfl_xor_sync(0xffffffffu, s,  o);
        ss += __shfl_xor_sync(0xffffffffu, ss, o);
    }
    __shared__ float sh[16];
    int w = threadIdx.x >> 5, ln = threadIdx.x & 31;
    if (ln == 0) { sh[w] = s; sh[w + 8] = ss; }
    __syncthreads();
    float fs = 0.f, fss = 0.f;
    #pragma unroll
    for (int k = 0; k < 8; k++) { fs += sh[k]; fss += sh[k + 8]; }
    float mu   = fs  * (1.f / DM);
    float var  = fss * (1.f / DM) - mu * mu;
    float rstd = rsqrtf(var + 1e-5f);

    const float* gp = gb + (size_t)row * gbStride + gbOff;
    float4 ga = *(const float4*)(gp + i);
    float4 be = *(const float4*)(gp + DM + i);
    float o0 = (v.x - mu) * rstd * (1.f + ga.x) + be.x;
    float o1 = (v.y - mu) * rstd * (1.f + ga.y) + be.y;
    float o2 = (v.z - mu) * rstd * (1.f + ga.z) + be.z;
    float o3 = (v.w - mu) * rstd * (1.f + ga.w) + be.w;
    __half2* op = (__half2*)(out + (size_t)row * DM + i);
    op[0] = __floats2half2_rn(o0, o1);
    op[1] = __floats2half2_rn(o2, o3);
}

// ---------------------------------------------------------------------------
// Launch
// ---------------------------------------------------------------------------
extern "C" void kernel_launch(void* const* d_in, const int* in_sizes, int n_in,
                              void* d_out, int out_size)
{
    const float* x          = (const float*)d_in[0];
    const float* cond       = (const float*)d_in[1];
    const float* p1_w       = (const float*)d_in[2];
    const float* p1_b       = (const float*)d_in[3];
    const float* qkv_w      = (const float*)d_in[4];
    const float* attn_out_w = (const float*)d_in[5];
    const float* p2_w       = (const float*)d_in[6];
    const float* p2_b       = (const float*)d_in[7];
    const float* ffn_w1     = (const float*)d_in[8];
    const float* ffn_b1     = (const float*)d_in[9];
    const float* ffn_w2     = (const float*)d_in[10];
    const float* ffn_b2     = (const float*)d_in[11];
    float* out = (float*)d_out;

    __half *sc, *h, *attn, *ff, *qkv;
    float *gb, *x2, *b_p12;
    __half *wt_p12, *wt_qkv, *wt_ao, *wt_f1, *wt_f2;
    cudaGetSymbolAddress((void**)&sc,     g_sc);
    cudaGetSymbolAddress((void**)&gb,     g_gb);
    cudaGetSymbolAddress((void**)&h,      g_h);
    cudaGetSymbolAddress((void**)&qkv,    g_qkv);
    cudaGetSymbolAddress((void**)&attn,   g_attn);
    cudaGetSymbolAddress((void**)&x2,     g_x2);
    cudaGetSymbolAddress((void**)&ff,     g_ff);
    cudaGetSymbolAddress((void**)&wt_p12, g_wt_p12);
    cudaGetSymbolAddress((void**)&wt_qkv, g_wt_qkv);
    cudaGetSymbolAddress((void**)&wt_ao,  g_wt_ao);
    cudaGetSymbolAddress((void**)&wt_f1,  g_wt_f1);
    cudaGetSymbolAddress((void**)&wt_f2,  g_wt_f2);
    cudaGetSymbolAddress((void**)&b_p12,  g_b_p12);

    cudaFuncSetAttribute(hgemm<1,0,0,0>, cudaFuncAttributeMaxDynamicSharedMemorySize, TG_SMEM);
    cudaFuncSetAttribute(hgemm<0,0,0,1>, cudaFuncAttributeMaxDynamicSharedMemorySize, TG_SMEM);
    cudaFuncSetAttribute(hgemm<0,0,1,0>, cudaFuncAttributeMaxDynamicSharedMemorySize, TG_SMEM);
    cudaFuncSetAttribute(hgemm<1,1,0,1>, cudaFuncAttributeMaxDynamicSharedMemorySize, TG_SMEM);
    cudaFuncSetAttribute(hgemm<1,0,1,0>, cudaFuncAttributeMaxDynamicSharedMemorySize, TG_SMEM);
    cudaFuncSetAttribute(fattn, cudaFuncAttributeMaxDynamicSharedMemorySize, ATT_SMEM);

    // Weight transposes: p1/p2 into one concatenated buffer
    transpose_h<<<dim3(2048/32,  512/32), 256>>>(p1_w, wt_p12,              512, 2048);
    transpose_h<<<dim3(2048/32,  512/32), 256>>>(p2_w, wt_p12 + 2048 * 512, 512, 2048);
    transpose_h<<<dim3(3072/32, 1024/32), 256>>>(qkv_w,      wt_qkv, 1024, 3072);
    transpose_h<<<dim3(1024/32, 1024/32), 256>>>(attn_out_w, wt_ao,  1024, 1024);
    transpose_h<<<dim3(4096/32, 1024/32), 256>>>(ffn_w1,     wt_f1,  1024, 4096);
    transpose_h<<<dim3(1024/32, 4096/32), 256>>>(ffn_w2,     wt_f2,  4096, 1024);
    concat_bias<<<(4 * DM + 255) / 256, 256>>>(p1_b, p2_b, b_p12);

    // 1. sc = silu(cond) -> fp16
    silu_kernel<<<(BS_TOK * DC / 4 + 255) / 256, 256>>>(cond, sc, BS_TOK * DC / 4);
    // 2. gb(all) = sc @ [p1_w|p2_w] + [p1_b|p2_b]   (M=4096, N=4096, K=512)
    hgemm<1,0,0,0><<<dim3(4096/128, BS_TOK/128), 256, TG_SMEM>>>(
        sc, wt_p12, b_p12, nullptr, gb, BS_TOK, 4096, DC);
    // 3. h = adaln(x, gb[:, 0:2048]) -> fp16
    adaln_kernel<<<BS_TOK, 256>>>(x, gb, 4096, 0, h);
    // 4. qkv = h @ qkv_w -> fp16
    hgemm<0,0,0,1><<<dim3(3072/128, BS_TOK/128), 256, TG_SMEM>>>(
        h, wt_qkv, nullptr, nullptr, qkv, BS_TOK, 3072, DM);
    // 5. attention -> fp16
    fattn<<<dim3(SEQ/128, NH, 2), 256, ATT_SMEM>>>(qkv, attn);
    // 6. x2 = x + attn @ attn_out_w (fp32 out)
    hgemm<0,0,1,0><<<dim3(1024/128, BS_TOK/128), 256, TG_SMEM>>>(
        attn, wt_ao, nullptr, x, x2, BS_TOK, 1024, DM);
    // 7. h = adaln(x2, gb[:, 2048:4096]) -> fp16
    adaln_kernel<<<BS_TOK, 256>>>(x2, gb, 4096, 2048, h);
    // 8. ff = gelu(h @ ffn_w1 + ffn_b1) -> fp16
    hgemm<1,1,0,1><<<dim3(DFF/128, BS_TOK/128), 256, TG_SMEM>>>(
        h, wt_f1, ffn_b1, nullptr, ff, BS_TOK, DFF, DM);
    // 9. out = x2 + ff @ ffn_w2 + ffn_b2 (fp32 out)
    hgemm<1,0,1,0><<<dim3(1024/128, BS_TOK/128), 256, TG_SMEM>>>(
        ff, wt_f2, ffn_b2, x2, out, BS_TOK, 1024, DFF);
}